// round 11
// baseline (speedup 1.0000x reference)
#include <cuda_runtime.h>
#include <cuda_bf16.h>
#include <mma.h>
#include <math.h>

using namespace nvcuda;

#define BATCH 16
#define P1H 97
#define P1W 383
#define C1 32
#define P2H 47
#define P2W 190
#define C2 64
#define FLAT 571520          // 47*190*64
#define KSLICE 640           // 893 * 640 = 571520 exactly
#define NSLICES 893
#define NCHUNK 80            // KSLICE / 8
#define FC_STAGES 3
#define FC_WLD 52                               // 48 cols + 4 pad floats per k-row
#define FC_STAGE_FLOATS (8 * FC_WLD)            // 416 floats per stage
#define FC_WARP_FLOATS (FC_STAGES * FC_STAGE_FLOATS)   // 1248
#define FC_SMEM_BYTES (16 * FC_WARP_FLOATS * 4)        // 79,872 B -> 2 CTAs/SM, ~68KB L1D left

// ---------------- scratch (device globals; allocations are forbidden) -------
__device__ __align__(128) __nv_bfloat16 g_x1b[(size_t)BATCH * P1H * P1W * C1]; // conv1 out bf16
__device__ __align__(16)  __nv_bfloat16 g_w2b[288 * 64];                       // conv2 weights bf16
__device__ __align__(128) float g_x2t[(size_t)FLAT * 16];                      // conv2 out TRANSPOSED [k][b]
__device__ float g_ypre[512 * 16];   // [n][b]
__device__ float g_zpre[256 * 16];
__device__ float g_y2[256 * 16];
__device__ float g_y3[2925 * 16];
__device__ float g_z4[64 * 16];
__device__ float g_z5[900 * 16];

__device__ __forceinline__ float leaky_f(float x) { return x >= 0.f ? x : 0.01f * x; }

// ---------------- prep: conv2 weight -> bf16 ; bias-init split-K accumulators
__global__ void prep_kernel(const float* __restrict__ w2,
                            const float* __restrict__ b512,
                            const float* __restrict__ b256b,
                            const float* __restrict__ bcls,
                            const float* __restrict__ b256a) {
    int i = blockIdx.x * 256 + threadIdx.x;
    if (i < 288 * 64) g_w2b[i] = __float2bfloat16(w2[i]);
    if (i < 512 * 16) g_ypre[i] = b512[i >> 4];
    if (i < 256 * 16) g_zpre[i] = b256b[i >> 4];
    if (i < 256 * 16) g_y2[i] = b256a[i >> 4];
    if (i < 2925 * 16) g_y3[i] = bcls[i >> 4];
}

// ---------------- conv1 (3x3, 1->32) + relu + maxpool2, fused, bf16 output --
__global__ void __launch_bounds__(256) conv1_kernel(const float* __restrict__ hidden,
                                                    const float* __restrict__ w1,
                                                    const float* __restrict__ b1) {
    __shared__ float ins[4 * 768];
    __shared__ float w1s[9 * 32];
    __shared__ float b1s[32];
    int b = blockIdx.y, ph = blockIdx.x;
    int tid = threadIdx.x;

    const float* src = hidden + ((size_t)b * 197 + 2 * ph) * 768;
    for (int i = tid; i < 4 * 768; i += 256) ins[i] = src[i];
    if (tid < 288) w1s[tid] = w1[tid];
    if (tid < 32) b1s[tid] = b1[tid];
    __syncthreads();

    int cg = tid >> 6;          // 0..3 (channel group of 8)
    int pwl = tid & 63;         // 0..63
    int c0 = cg * 8;

    float wv[9][8];
#pragma unroll
    for (int t = 0; t < 9; t++)
#pragma unroll
        for (int cc = 0; cc < 8; cc++) wv[t][cc] = w1s[t * 32 + c0 + cc];

    for (int it = 0; it < 6; it++) {
        int pw = it * 64 + pwl;
        if (pw >= 383) break;
        float in[4][4];
#pragma unroll
        for (int r = 0; r < 4; r++)
#pragma unroll
            for (int c = 0; c < 4; c++) in[r][c] = ins[r * 768 + 2 * pw + c];

        float acc[2][2][8];
#pragma unroll
        for (int i = 0; i < 2; i++)
#pragma unroll
            for (int j = 0; j < 2; j++)
#pragma unroll
                for (int cc = 0; cc < 8; cc++) acc[i][j][cc] = 0.f;

#pragma unroll
        for (int t = 0; t < 9; t++) {
            int kh = t / 3, kw = t % 3;
#pragma unroll
            for (int i = 0; i < 2; i++)
#pragma unroll
                for (int j = 0; j < 2; j++) {
                    float x = in[i + kh][j + kw];
#pragma unroll
                    for (int cc = 0; cc < 8; cc++)
                        acc[i][j][cc] = fmaf(x, wv[t][cc], acc[i][j][cc]);
                }
        }

        size_t o = (((size_t)b * P1H + ph) * P1W + pw) * C1 + c0;
        __nv_bfloat162* dst = reinterpret_cast<__nv_bfloat162*>(g_x1b + o);
#pragma unroll
        for (int t = 0; t < 4; t++) {
            int cc = 2 * t;
            float m0 = fmaxf(fmaxf(acc[0][0][cc],     acc[0][1][cc]),
                             fmaxf(acc[1][0][cc],     acc[1][1][cc]));
            float m1 = fmaxf(fmaxf(acc[0][0][cc + 1], acc[0][1][cc + 1]),
                             fmaxf(acc[1][0][cc + 1], acc[1][1][cc + 1]));
            dst[t] = __floats2bfloat162_rn(fmaxf(m0 + b1s[c0 + cc], 0.f),
                                           fmaxf(m1 + b1s[c0 + cc + 1], 0.f));
        }
    }
}

// ---------------- conv2 (3x3, 32->64) bf16 wmma implicit GEMM + relu + pool --
// Output written TRANSPOSED to g_x2t[k][b] so fcbig's A tiles are contiguous.
#define CV2_BPAD 72
__global__ void __launch_bounds__(256) conv2_kernel(const float* __restrict__ b2) {
    extern __shared__ __align__(16) __nv_bfloat16 smem_h[];
    __nv_bfloat16* x1s = smem_h;                 // 6*1088 halfs = 13056 B
    __nv_bfloat16* w2s = smem_h + 6 * 1088;      // 288*72 halfs = 41472 B

    int wt = blockIdx.x;        // 0..11
    int pb = blockIdx.y;        // 0..23
    int b = blockIdx.z;         // 0..15
    int tid = threadIdx.x;
    int h0 = 4 * pb;
    int w0 = wt * 32;

    // stage A: 6 rows x 136 uint4 (border-clamped; clamped data only feeds discarded outputs)
    for (int i = tid; i < 6 * 136; i += 256) {
        int r = i / 136, q = i - r * 136;
        int row = h0 + r; if (row > 96) row = 96;
        int col = w0 + (q >> 2); if (col > 382) col = 382;
        const uint4 v = *(const uint4*)(g_x1b + (((size_t)b * P1H + row) * P1W + col) * C1 + (q & 3) * 8);
        *(uint4*)(x1s + (size_t)r * 1088 + q * 8) = v;
    }
    // stage B with row padding 64->72: 288 rows x 8 uint4 (8 halves each)
    for (int i = tid; i < 2304; i += 256) {
        int k = i >> 3, n0 = (i & 7) * 8;
        uint4 v = *(const uint4*)(g_w2b + k * 64 + n0);
        *(uint4*)(w2s + k * CV2_BPAD + n0) = v;
    }
    __syncthreads();

    int wid = tid >> 5;
    int rloc = wid >> 1;            // conv-row offset 0..3
    int wOff = (wid & 1) * 16;      // col half

    wmma::fragment<wmma::matrix_a, 16, 16, 16, __nv_bfloat16, wmma::row_major> af;
    wmma::fragment<wmma::matrix_b, 16, 16, 16, __nv_bfloat16, wmma::row_major> bf;
    wmma::fragment<wmma::accumulator, 16, 16, 16, float> acc[4];
#pragma unroll
    for (int nf = 0; nf < 4; nf++) wmma::fill_fragment(acc[nf], 0.f);

#pragma unroll
    for (int kh = 0; kh < 3; kh++) {
        const __nv_bfloat16* ap = x1s + (rloc + kh) * 1088 + wOff * 32;
#pragma unroll
        for (int jc = 0; jc < 6; jc++) {
            wmma::load_matrix_sync(af, ap + jc * 16, 32);
            const __nv_bfloat16* bp = w2s + (kh * 96 + jc * 16) * CV2_BPAD;
#pragma unroll
            for (int nf = 0; nf < 4; nf++) {
                wmma::load_matrix_sync(bf, bp + nf * 16, CV2_BPAD);
                wmma::mma_sync(acc[nf], af, bf, acc[nf]);
            }
        }
    }

    __syncthreads();                 // B fully consumed -> reuse as C (fp32)
    float* cs = reinterpret_cast<float*>(w2s);   // 8 x 1024 floats = 32 KB
#pragma unroll
    for (int nf = 0; nf < 4; nf++)
        wmma::store_matrix_sync(cs + wid * 1024 + nf * 16, acc[nf], 64, wmma::mem_row_major);
    __syncthreads();

    // pooling epilogue: tid -> (pr 0..1, pj 0..15, 8 channels); writes g_x2t[k][b]
    int pr = tid >> 7;
    int pj = (tid >> 3) & 15;
    int c0 = (tid & 7) * 8;
    int ph2 = 2 * pb + pr;
    int pwg = wt * 16 + pj;
    if (ph2 < P2H && pwg < P2W) {
        size_t kbase = ((size_t)ph2 * P2W + pwg) * C2 + c0;
#pragma unroll
        for (int cc = 0; cc < 8; cc++) {
            int c = c0 + cc;
            float m = -1e30f;
#pragma unroll
            for (int i = 0; i < 2; i++)
#pragma unroll
                for (int j = 0; j < 2; j++) {
                    int rr = 2 * pr + i;
                    int jj = 2 * pj + j;
                    m = fmaxf(m, cs[(rr * 2 + (jj >> 4)) * 1024 + (jj & 15) * 64 + c]);
                }
            g_x2t[(kbase + cc) * 16 + b] = fmaxf(m + b2[c], 0.f);
        }
    }
}

// ---------------- big FC via TF32 tensor cores, warp-private cp.async rings --
// D[16, 768] += x[16, K] @ (w512 | w256b), split-K over 893 slices.
// 512 thr / 16 warps, 2 CTAs/SM. Warp w owns cols [48w, 48w+48) in a private
// 3-stage ring (prefetch depth 2). A tile for chunk c is the CONTIGUOUS 512B
// block g_x2t[(k0+8c)*16 ..] (col_major, ld=16) — one L1 line shared by all
// warps. NO CTA barriers anywhere.
__global__ void __launch_bounds__(512, 2) fcbig_tf32_kernel(const float* __restrict__ w512,
                                                            const float* __restrict__ w256b) {
    extern __shared__ __align__(16) float ws[];  // [16 warps][3 stages][8][FC_WLD]

    int tid = threadIdx.x;
    int wid = tid >> 5;
    int lane = tid & 31;
    size_t k0 = (size_t)blockIdx.x * KSLICE;

    // per-thread cp.async precompute: 3 x 16B per chunk over [8 rows][12 float4]
    const float* gsrc[3];
    int gstep[3];
    unsigned soff[3];
#pragma unroll
    for (int i = 0; i < 3; i++) {
        int idx = lane + i * 32;              // 0..95
        int r = idx / 12;
        int c4 = idx - r * 12;
        int gcol = wid * 48 + c4 * 4;
        if (gcol < 512) { gsrc[i] = w512  + (k0 + r) * 512 + gcol;         gstep[i] = 8 * 512; }
        else            { gsrc[i] = w256b + (k0 + r) * 256 + (gcol - 512); gstep[i] = 8 * 256; }
        soff[i] = (unsigned)((r * FC_WLD + c4 * 4) * 4);
    }
    unsigned wbase = (unsigned)__cvta_generic_to_shared(ws) + wid * (FC_WARP_FLOATS * 4);

#define FC_ISSUE(c)                                                               \
    {                                                                             \
        unsigned sb = wbase + ((c) % FC_STAGES) * (FC_STAGE_FLOATS * 4);          \
        _Pragma("unroll")                                                         \
        for (int i = 0; i < 3; i++) {                                             \
            const float* g = gsrc[i] + (size_t)(c) * gstep[i];                    \
            asm volatile("cp.async.cg.shared.global [%0], [%1], 16;"              \
                         :: "r"(sb + soff[i]), "l"(g));                           \
        }                                                                         \
        asm volatile("cp.async.commit_group;");                                   \
    }

    FC_ISSUE(0); FC_ISSUE(1);

    wmma::fragment<wmma::matrix_a, 16, 16, 8, wmma::precision::tf32, wmma::col_major> af;
    wmma::fragment<wmma::matrix_b, 16, 16, 8, wmma::precision::tf32, wmma::row_major> bfr;
    wmma::fragment<wmma::accumulator, 16, 16, 8, float> acc[3];
#pragma unroll
    for (int t = 0; t < 3; t++) wmma::fill_fragment(acc[t], 0.f);

    const float* wsw = ws + wid * FC_WARP_FLOATS;
    const float* abase = g_x2t + k0 * 16;        // A[m][kk] = abase[(c*8+kk)*16 + m]
    for (int c = 0; c < NCHUNK; c++) {
        asm volatile("cp.async.wait_group 1;");
        __syncwarp();                            // warp-local visibility of chunk c

        wmma::load_matrix_sync(af, abase + (size_t)c * 128, 16);  // 512B contiguous
        const float* buf = wsw + (c % FC_STAGES) * FC_STAGE_FLOATS;
#pragma unroll
        for (int t = 0; t < 3; t++) {
            wmma::load_matrix_sync(bfr, buf + t * 16, FC_WLD);
            wmma::mma_sync(acc[t], af, bfr, acc[t]);
        }

        if (c + 2 < NCHUNK) FC_ISSUE(c + 2);
    }
    asm volatile("cp.async.wait_group 0;");
    __syncwarp();

    // epilogue (barrier-free): each warp reuses its own ring as the patch buffer
    float* patch = ws + wid * FC_WARP_FLOATS;    // 256 floats needed, 1248 available
#pragma unroll
    for (int t = 0; t < 3; t++) {
        wmma::store_matrix_sync(patch, acc[t], 16, wmma::mem_row_major);
        __syncwarp();
        int gcb = wid * 48 + t * 16;
#pragma unroll
        for (int u = 0; u < 8; u++) {
            int e = lane + u * 32;
            int m = e >> 4, n = e & 15;
            int gcol = gcb + n;
            float val = patch[e];
            float* dst = (gcol < 512) ? (g_ypre + gcol * 16 + m)
                                      : (g_zpre + (gcol - 512) * 16 + m);
            atomicAdd(dst, val);
        }
        __syncwarp();
    }
#undef FC_ISSUE
}

// ---------------- small FC: outPre[n2][b] = bias[n2] + sum_k leaky(inPre[k][b]) w[k][n2]
template <int K>
__global__ void __launch_bounds__(128) smallfc_kernel(const float* __restrict__ inPre,
                                                      const float* __restrict__ w,
                                                      const float* __restrict__ bias,
                                                      float* __restrict__ outPre,
                                                      int N2) {
    __shared__ float xs[K * 16];
    int tid = threadIdx.x;
    for (int idx = tid; idx < K * 16; idx += 128) xs[idx] = leaky_f(inPre[idx]);
    __syncthreads();

    int n2 = blockIdx.x * 128 + tid;
    if (n2 < N2) {
        float acc[16];
#pragma unroll
        for (int b = 0; b < 16; b++) acc[b] = 0.f;
#pragma unroll 8
        for (int k = 0; k < K; k++) {
            float wv = __ldg(w + (size_t)k * N2 + n2);
#pragma unroll
            for (int b = 0; b < 16; b++) acc[b] = fmaf(wv, xs[k * 16 + b], acc[b]);
        }
        float bb = bias[n2];
#pragma unroll
        for (int b = 0; b < 16; b++) outPre[n2 * 16 + b] = acc[b] + bb;
    }
}

// ---------------- split-K small FC (128-row K slices), out pre-initialized with bias
__global__ void __launch_bounds__(128) splitfc_kernel(const float* __restrict__ inPre,
                                                      const float* __restrict__ w,
                                                      float* __restrict__ outAcc,
                                                      int N2) {
    __shared__ float xs[128 * 16];
    int tid = threadIdx.x;
    int kh = blockIdx.y;                    // k in [kh*128, kh*128+128)
    const float* ip = inPre + kh * 128 * 16;
    for (int idx = tid; idx < 128 * 16; idx += 128) xs[idx] = leaky_f(ip[idx]);
    __syncthreads();

    int n2 = blockIdx.x * 128 + tid;
    if (n2 < N2) {
        float acc[16];
#pragma unroll
        for (int b = 0; b < 16; b++) acc[b] = 0.f;
        const float* wp = w + (size_t)kh * 128 * N2 + n2;
#pragma unroll 8
        for (int k = 0; k < 128; k++) {
            float wv = __ldg(wp + (size_t)k * N2);
#pragma unroll
            for (int b = 0; b < 16; b++) acc[b] = fmaf(wv, xs[k * 16 + b], acc[b]);
        }
#pragma unroll
        for (int b = 0; b < 16; b++) atomicAdd(outAcc + n2 * 16 + b, acc[b]);
    }
}

// ---------------- fused z-chain: 256 ->128 ->128 ->64, one CTA ---------------
__global__ void __launch_bounds__(128) zfused_kernel(const float* __restrict__ w128a,
                                                     const float* __restrict__ b128a,
                                                     const float* __restrict__ w128b,
                                                     const float* __restrict__ b128b,
                                                     const float* __restrict__ w64,
                                                     const float* __restrict__ b64) {
    __shared__ float xa[256 * 16];
    __shared__ float xb[128 * 16];
    int tid = threadIdx.x;
    for (int idx = tid; idx < 256 * 16; idx += 128) xa[idx] = leaky_f(g_zpre[idx]);
    __syncthreads();

    {
        float acc[16];
#pragma unroll
        for (int b = 0; b < 16; b++) acc[b] = 0.f;
#pragma unroll 8
        for (int k = 0; k < 256; k++) {
            float wv = __ldg(w128a + (size_t)k * 128 + tid);
#pragma unroll
            for (int b = 0; b < 16; b++) acc[b] = fmaf(wv, xa[k * 16 + b], acc[b]);
        }
        float bb = b128a[tid];
#pragma unroll
        for (int b = 0; b < 16; b++) xb[tid * 16 + b] = leaky_f(acc[b] + bb);
    }
    __syncthreads();

    {
        float acc[16];
#pragma unroll
        for (int b = 0; b < 16; b++) acc[b] = 0.f;
#pragma unroll 8
        for (int k = 0; k < 128; k++) {
            float wv = __ldg(w128b + (size_t)k * 128 + tid);
#pragma unroll
            for (int b = 0; b < 16; b++) acc[b] = fmaf(wv, xb[k * 16 + b], acc[b]);
        }
        float bb = b128b[tid];
#pragma unroll
        for (int b = 0; b < 16; b++) xa[tid * 16 + b] = leaky_f(acc[b] + bb);
    }
    __syncthreads();

    if (tid < 64) {
        float acc[16];
#pragma unroll
        for (int b = 0; b < 16; b++) acc[b] = 0.f;
#pragma unroll 8
        for (int k = 0; k < 128; k++) {
            float wv = __ldg(w64 + (size_t)k * 64 + tid);
#pragma unroll
            for (int b = 0; b < 16; b++) acc[b] = fmaf(wv, xa[k * 16 + b], acc[b]);
        }
        float bb = b64[tid];
#pragma unroll
        for (int b = 0; b < 16; b++) g_z4[tid * 16 + b] = acc[b] + bb;
    }
}

// ---------------- heads: softmax(leaky(y3)@wsm+bsm), sigmoid(leaky(z5)@wsig+bsig)
__global__ void heads_kernel(const float* __restrict__ wsm, const float* __restrict__ bsm,
                             const float* __restrict__ wsig, const float* __restrict__ bsig,
                             float* __restrict__ out) {
    int idx = blockIdx.x * 256 + threadIdx.x;
    if (idx < 3600) {
        int b = idx / 225, p = idx % 225;
        float yv[13];
#pragma unroll
        for (int i = 0; i < 13; i++) yv[i] = leaky_f(g_y3[(p * 13 + i) * 16 + b]);
        float l[13];
        float m = -1e30f;
#pragma unroll
        for (int o = 0; o < 13; o++) {
            float s = bsm[o];
#pragma unroll
            for (int i = 0; i < 13; i++) s = fmaf(yv[i], wsm[i * 13 + o], s);
            l[o] = s;
            m = fmaxf(m, s);
        }
        float sum = 0.f;
#pragma unroll
        for (int o = 0; o < 13; o++) { l[o] = expf(l[o] - m); sum += l[o]; }
        float inv = 1.f / sum;
        float* dst = out + (size_t)(b * 225 + p) * 13;
#pragma unroll
        for (int o = 0; o < 13; o++) dst[o] = l[o] * inv;
    } else if (idx < 7200) {
        int j = idx - 3600;
        int b = j / 225, p = j % 225;
        float zv[4];
#pragma unroll
        for (int i = 0; i < 4; i++) zv[i] = leaky_f(g_z5[(p * 4 + i) * 16 + b]);
        float* dst = out + 46800 + (size_t)(b * 225 + p) * 4;
#pragma unroll
        for (int o = 0; o < 4; o++) {
            float s = bsig[o];
#pragma unroll
            for (int i = 0; i < 4; i++) s = fmaf(zv[i], wsig[i * 4 + o], s);
            dst[o] = 1.f / (1.f + expf(-s));
        }
    }
}

// ---------------- launch ----------------------------------------------------
extern "C" void kernel_launch(void* const* d_in, const int* in_sizes, int n_in,
                              void* d_out, int out_size) {
    const float* hidden  = (const float*)d_in[0];
    const float* conv1_w = (const float*)d_in[1];
    const float* conv1_b = (const float*)d_in[2];
    const float* conv2_w = (const float*)d_in[3];
    const float* conv2_b = (const float*)d_in[4];
    const float* w512    = (const float*)d_in[5];
    const float* b512    = (const float*)d_in[6];
    const float* w256a   = (const float*)d_in[7];
    const float* b256a   = (const float*)d_in[8];
    const float* wcls    = (const float*)d_in[9];
    const float* bcls    = (const float*)d_in[10];
    const float* wsm     = (const float*)d_in[11];
    const float* bsm     = (const float*)d_in[12];
    const float* w256b   = (const float*)d_in[13];
    const float* b256b   = (const float*)d_in[14];
    const float* w128a   = (const float*)d_in[15];
    const float* b128a   = (const float*)d_in[16];
    const float* w128b   = (const float*)d_in[17];
    const float* b128b   = (const float*)d_in[18];
    const float* w64     = (const float*)d_in[19];
    const float* b64     = (const float*)d_in[20];
    const float* wreg    = (const float*)d_in[21];
    const float* breg    = (const float*)d_in[22];
    const float* wsig    = (const float*)d_in[23];
    const float* bsig    = (const float*)d_in[24];
    float* out = (float*)d_out;

    float *ypre, *y2, *y3, *z4, *z5;
    cudaGetSymbolAddress((void**)&ypre, g_ypre);
    cudaGetSymbolAddress((void**)&y2, g_y2);
    cudaGetSymbolAddress((void**)&y3, g_y3);
    cudaGetSymbolAddress((void**)&z4, g_z4);
    cudaGetSymbolAddress((void**)&z5, g_z5);

    static bool attr_set = false;
    if (!attr_set) {
        cudaFuncSetAttribute(conv2_kernel, cudaFuncAttributeMaxDynamicSharedMemorySize, 54528);
        cudaFuncSetAttribute(fcbig_tf32_kernel, cudaFuncAttributeMaxDynamicSharedMemorySize, FC_SMEM_BYTES);
        attr_set = true;
    }

    prep_kernel<<<183, 256>>>(conv2_w, b512, b256b, bcls, b256a);
    conv1_kernel<<<dim3(P1H, BATCH), 256>>>(hidden, conv1_w, conv1_b);
    conv2_kernel<<<dim3(12, 24, BATCH), 256, 54528>>>(conv2_b);
    fcbig_tf32_kernel<<<NSLICES, 512, FC_SMEM_BYTES>>>(w512, w256b);

    splitfc_kernel<<<dim3(2, 4), 128>>>(ypre, w256a, y2, 256);
    splitfc_kernel<<<dim3(23, 2), 128>>>(y2, wcls, y3, 2925);
    zfused_kernel<<<1, 128>>>(w128a, b128a, w128b, b128b, w64, b64);
    smallfc_kernel<64><<<8, 128>>>(z4, wreg, breg, z5, 900);

    heads_kernel<<<29, 256>>>(wsm, bsm, wsig, bsig, out);
}

// round 12
// speedup vs baseline: 1.1515x; 1.1515x over previous
#include <cuda_runtime.h>
#include <cuda_bf16.h>
#include <mma.h>
#include <math.h>

using namespace nvcuda;

#define BATCH 16
#define P1H 97
#define P1W 383
#define C1 32
#define P2H 47
#define P2W 190
#define C2 64
#define FLAT 571520          // 47*190*64
#define KSLICE 640           // 893 * 640 = 571520 exactly
#define NSLICES 893
#define NCHUNK 80            // KSLICE / 8
#define FC_STAGES 3
#define FC_WLD 52                               // 48 cols + 4 pad floats per k-row
#define FC_STAGE_FLOATS (8 * FC_WLD)            // 416 floats per stage
#define FC_WARP_FLOATS (FC_STAGES * FC_STAGE_FLOATS)   // 1248
#define FC_SMEM_BYTES (16 * FC_WARP_FLOATS * 4)        // 79,872 B -> 2 CTAs/SM, ~68KB L1D left

// ---------------- scratch (device globals; allocations are forbidden) -------
__device__ __align__(128) __nv_bfloat16 g_x1b[(size_t)BATCH * P1H * P1W * C1]; // conv1 out bf16
__device__ __align__(16)  __nv_bfloat16 g_w2b[288 * 64];                       // conv2 weights bf16
__device__ __align__(16)  float g_x2[(size_t)BATCH * FLAT];                    // conv2 out [b][k]
__device__ float g_ypre[512 * 16];   // [n][b]
__device__ float g_zpre[256 * 16];
__device__ float g_y2[256 * 16];
__device__ float g_y3[2925 * 16];
__device__ float g_z4[64 * 16];
__device__ float g_z5[900 * 16];

__device__ __forceinline__ float leaky_f(float x) { return x >= 0.f ? x : 0.01f * x; }

__device__ __forceinline__ unsigned long long pack2(float a, float b) {
    unsigned long long r;
    asm("mov.b64 %0, {%1, %2};" : "=l"(r) : "f"(a), "f"(b));
    return r;
}
__device__ __forceinline__ float2 unpack2(unsigned long long v) {
    float2 r;
    asm("mov.b64 {%0, %1}, %2;" : "=f"(r.x), "=f"(r.y) : "l"(v));
    return r;
}
__device__ __forceinline__ void ffma2(unsigned long long& acc, unsigned long long a, unsigned long long b) {
    asm("fma.rn.f32x2 %0, %1, %2, %0;" : "+l"(acc) : "l"(a), "l"(b));
}

// ---------------- prep: conv2 weight -> bf16 ; bias-init split-K accumulators
__global__ void prep_kernel(const float* __restrict__ w2,
                            const float* __restrict__ b512,
                            const float* __restrict__ b256b,
                            const float* __restrict__ bcls,
                            const float* __restrict__ b256a) {
    int i = blockIdx.x * 256 + threadIdx.x;
    if (i < 288 * 64) g_w2b[i] = __float2bfloat16(w2[i]);
    if (i < 512 * 16) g_ypre[i] = b512[i >> 4];
    if (i < 256 * 16) g_zpre[i] = b256b[i >> 4];
    if (i < 256 * 16) g_y2[i] = b256a[i >> 4];
    if (i < 2925 * 16) g_y3[i] = bcls[i >> 4];
}

// ---------------- conv1 (3x3, 1->32) + relu + maxpool2, fused, bf16 output --
// Channel pairs packed into fma.rn.f32x2 — half the FMA issue count.
__global__ void __launch_bounds__(256) conv1_kernel(const float* __restrict__ hidden,
                                                    const float* __restrict__ w1,
                                                    const float* __restrict__ b1) {
    __shared__ float ins[4 * 768];
    __shared__ float w1s[9 * 32];
    __shared__ float b1s[32];
    int b = blockIdx.y, ph = blockIdx.x;
    int tid = threadIdx.x;

    const float* src = hidden + ((size_t)b * 197 + 2 * ph) * 768;
    for (int i = tid; i < 4 * 768; i += 256) ins[i] = src[i];
    if (tid < 288) w1s[tid] = w1[tid];
    if (tid < 32) b1s[tid] = b1[tid];
    __syncthreads();

    int cg = tid >> 6;          // 0..3 (channel group of 8 = 4 pairs)
    int pwl = tid & 63;         // 0..63
    int c0 = cg * 8;

    unsigned long long wv2[9][4];
#pragma unroll
    for (int t = 0; t < 9; t++)
#pragma unroll
        for (int p = 0; p < 4; p++)
            wv2[t][p] = pack2(w1s[t * 32 + c0 + 2 * p], w1s[t * 32 + c0 + 2 * p + 1]);

    for (int it = 0; it < 6; it++) {
        int pw = it * 64 + pwl;
        if (pw >= 383) break;
        float in[4][4];
#pragma unroll
        for (int r = 0; r < 4; r++)
#pragma unroll
            for (int c = 0; c < 4; c++) in[r][c] = ins[r * 768 + 2 * pw + c];

        unsigned long long acc2[2][2][4];
#pragma unroll
        for (int i = 0; i < 2; i++)
#pragma unroll
            for (int j = 0; j < 2; j++)
#pragma unroll
                for (int p = 0; p < 4; p++) acc2[i][j][p] = 0ull;

#pragma unroll
        for (int t = 0; t < 9; t++) {
            int kh = t / 3, kw = t % 3;
#pragma unroll
            for (int i = 0; i < 2; i++)
#pragma unroll
                for (int j = 0; j < 2; j++) {
                    float x = in[i + kh][j + kw];
                    unsigned long long xx = pack2(x, x);
#pragma unroll
                    for (int p = 0; p < 4; p++)
                        ffma2(acc2[i][j][p], wv2[t][p], xx);
                }
        }

        size_t o = (((size_t)b * P1H + ph) * P1W + pw) * C1 + c0;
        __nv_bfloat162* dst = reinterpret_cast<__nv_bfloat162*>(g_x1b + o);
#pragma unroll
        for (int p = 0; p < 4; p++) {
            float2 a00 = unpack2(acc2[0][0][p]);
            float2 a01 = unpack2(acc2[0][1][p]);
            float2 a10 = unpack2(acc2[1][0][p]);
            float2 a11 = unpack2(acc2[1][1][p]);
            float m0 = fmaxf(fmaxf(a00.x, a01.x), fmaxf(a10.x, a11.x));
            float m1 = fmaxf(fmaxf(a00.y, a01.y), fmaxf(a10.y, a11.y));
            dst[p] = __floats2bfloat162_rn(fmaxf(m0 + b1s[c0 + 2 * p], 0.f),
                                           fmaxf(m1 + b1s[c0 + 2 * p + 1], 0.f));
        }
    }
}

// ---------------- conv2 (3x3, 32->64) bf16 wmma implicit GEMM + relu + pool --
#define CV2_BPAD 72
__global__ void __launch_bounds__(256) conv2_kernel(const float* __restrict__ b2) {
    extern __shared__ __align__(16) __nv_bfloat16 smem_h[];
    __nv_bfloat16* x1s = smem_h;                 // 6*1088 halfs = 13056 B
    __nv_bfloat16* w2s = smem_h + 6 * 1088;      // 288*72 halfs = 41472 B

    int wt = blockIdx.x;        // 0..11
    int pb = blockIdx.y;        // 0..23
    int b = blockIdx.z;         // 0..15
    int tid = threadIdx.x;
    int h0 = 4 * pb;
    int w0 = wt * 32;

    // stage A: 6 rows x 136 uint4 (border-clamped; clamped data only feeds discarded outputs)
    for (int i = tid; i < 6 * 136; i += 256) {
        int r = i / 136, q = i - r * 136;
        int row = h0 + r; if (row > 96) row = 96;
        int col = w0 + (q >> 2); if (col > 382) col = 382;
        const uint4 v = *(const uint4*)(g_x1b + (((size_t)b * P1H + row) * P1W + col) * C1 + (q & 3) * 8);
        *(uint4*)(x1s + (size_t)r * 1088 + q * 8) = v;
    }
    // stage B with row padding 64->72: 288 rows x 8 uint4 (8 halves each)
    for (int i = tid; i < 2304; i += 256) {
        int k = i >> 3, n0 = (i & 7) * 8;
        uint4 v = *(const uint4*)(g_w2b + k * 64 + n0);
        *(uint4*)(w2s + k * CV2_BPAD + n0) = v;
    }
    __syncthreads();

    int wid = tid >> 5;
    int rloc = wid >> 1;            // conv-row offset 0..3
    int wOff = (wid & 1) * 16;      // col half

    wmma::fragment<wmma::matrix_a, 16, 16, 16, __nv_bfloat16, wmma::row_major> af;
    wmma::fragment<wmma::matrix_b, 16, 16, 16, __nv_bfloat16, wmma::row_major> bf;
    wmma::fragment<wmma::accumulator, 16, 16, 16, float> acc[4];
#pragma unroll
    for (int nf = 0; nf < 4; nf++) wmma::fill_fragment(acc[nf], 0.f);

#pragma unroll
    for (int kh = 0; kh < 3; kh++) {
        const __nv_bfloat16* ap = x1s + (rloc + kh) * 1088 + wOff * 32;
#pragma unroll
        for (int jc = 0; jc < 6; jc++) {
            wmma::load_matrix_sync(af, ap + jc * 16, 32);
            const __nv_bfloat16* bp = w2s + (kh * 96 + jc * 16) * CV2_BPAD;
#pragma unroll
            for (int nf = 0; nf < 4; nf++) {
                wmma::load_matrix_sync(bf, bp + nf * 16, CV2_BPAD);
                wmma::mma_sync(acc[nf], af, bf, acc[nf]);
            }
        }
    }

    __syncthreads();                 // B fully consumed -> reuse as C (fp32)
    float* cs = reinterpret_cast<float*>(w2s);   // 8 x 1024 floats = 32 KB
#pragma unroll
    for (int nf = 0; nf < 4; nf++)
        wmma::store_matrix_sync(cs + wid * 1024 + nf * 16, acc[nf], 64, wmma::mem_row_major);
    __syncthreads();

    // pooling epilogue: tid -> (pr 0..1, pj 0..15, 8 channels)
    int pr = tid >> 7;
    int pj = (tid >> 3) & 15;
    int c0 = (tid & 7) * 8;
    int ph2 = 2 * pb + pr;
    int pwg = wt * 16 + pj;
    if (ph2 < P2H && pwg < P2W) {
        float v[8];
#pragma unroll
        for (int cc = 0; cc < 8; cc++) {
            int c = c0 + cc;
            float m = -1e30f;
#pragma unroll
            for (int i = 0; i < 2; i++)
#pragma unroll
                for (int j = 0; j < 2; j++) {
                    int rr = 2 * pr + i;
                    int jj = 2 * pj + j;
                    m = fmaxf(m, cs[(rr * 2 + (jj >> 4)) * 1024 + (jj & 15) * 64 + c]);
                }
            v[cc] = fmaxf(m + b2[c], 0.f);
        }
        size_t o = (size_t)b * FLAT + ((size_t)ph2 * P2W + pwg) * C2 + c0;
        float4 o0 = {v[0], v[1], v[2], v[3]};
        float4 o1 = {v[4], v[5], v[6], v[7]};
        *reinterpret_cast<float4*>(g_x2 + o) = o0;
        *reinterpret_cast<float4*>(g_x2 + o + 4) = o1;
    }
}

// ---------------- big FC via TF32 tensor cores, warp-private cp.async rings --
// D[16, 768] += x[16, K] @ (w512 | w256b), split-K over 893 slices.
// 512 thr / 16 warps, 2 CTAs/SM. Warp w owns cols [48w, 48w+48) in a private
// 3-stage ring (prefetch depth 2). A fragments load DIRECTLY from g_x2
// (row-major, ld=FLAT, m=batch) — each chunk's 512B is L1-shared by all warps.
// NO CTA barriers anywhere.  [R9-verbatim: best measured 342us]
__global__ void __launch_bounds__(512, 2) fcbig_tf32_kernel(const float* __restrict__ w512,
                                                            const float* __restrict__ w256b) {
    extern __shared__ __align__(16) float ws[];  // [16 warps][3 stages][8][FC_WLD]

    int tid = threadIdx.x;
    int wid = tid >> 5;
    int lane = tid & 31;
    size_t k0 = (size_t)blockIdx.x * KSLICE;

    // per-thread cp.async precompute: 3 x 16B per chunk over [8 rows][12 float4]
    const float* gsrc[3];
    int gstep[3];
    unsigned soff[3];
#pragma unroll
    for (int i = 0; i < 3; i++) {
        int idx = lane + i * 32;              // 0..95
        int r = idx / 12;
        int c4 = idx - r * 12;
        int gcol = wid * 48 + c4 * 4;
        if (gcol < 512) { gsrc[i] = w512  + (k0 + r) * 512 + gcol;         gstep[i] = 8 * 512; }
        else            { gsrc[i] = w256b + (k0 + r) * 256 + (gcol - 512); gstep[i] = 8 * 256; }
        soff[i] = (unsigned)((r * FC_WLD + c4 * 4) * 4);
    }
    unsigned wbase = (unsigned)__cvta_generic_to_shared(ws) + wid * (FC_WARP_FLOATS * 4);

#define FC_ISSUE(c)                                                               \
    {                                                                             \
        unsigned sb = wbase + ((c) % FC_STAGES) * (FC_STAGE_FLOATS * 4);          \
        _Pragma("unroll")                                                         \
        for (int i = 0; i < 3; i++) {                                             \
            const float* g = gsrc[i] + (size_t)(c) * gstep[i];                    \
            asm volatile("cp.async.cg.shared.global [%0], [%1], 16;"              \
                         :: "r"(sb + soff[i]), "l"(g));                           \
        }                                                                         \
        asm volatile("cp.async.commit_group;");                                   \
    }

    FC_ISSUE(0); FC_ISSUE(1);

    wmma::fragment<wmma::matrix_a, 16, 16, 8, wmma::precision::tf32, wmma::row_major> af;
    wmma::fragment<wmma::matrix_b, 16, 16, 8, wmma::precision::tf32, wmma::row_major> bfr;
    wmma::fragment<wmma::accumulator, 16, 16, 8, float> acc[3];
#pragma unroll
    for (int t = 0; t < 3; t++) wmma::fill_fragment(acc[t], 0.f);

    const float* wsw = ws + wid * FC_WARP_FLOATS;
    const float* abase = g_x2 + k0;              // A[m][kk] = abase[m*FLAT + c*8 + kk]
    for (int c = 0; c < NCHUNK; c++) {
        asm volatile("cp.async.wait_group 1;");
        __syncwarp();                            // warp-local visibility of chunk c

        wmma::load_matrix_sync(af, abase + c * 8, FLAT);   // gmem, L1-shared
        const float* buf = wsw + (c % FC_STAGES) * FC_STAGE_FLOATS;
#pragma unroll
        for (int t = 0; t < 3; t++) {
            wmma::load_matrix_sync(bfr, buf + t * 16, FC_WLD);
            wmma::mma_sync(acc[t], af, bfr, acc[t]);
        }

        if (c + 2 < NCHUNK) FC_ISSUE(c + 2);
    }
    asm volatile("cp.async.wait_group 0;");
    __syncwarp();

    // epilogue (barrier-free): each warp reuses its own ring as the patch buffer
    float* patch = ws + wid * FC_WARP_FLOATS;    // 256 floats needed, 1248 available
#pragma unroll
    for (int t = 0; t < 3; t++) {
        wmma::store_matrix_sync(patch, acc[t], 16, wmma::mem_row_major);
        __syncwarp();
        int gcb = wid * 48 + t * 16;
#pragma unroll
        for (int u = 0; u < 8; u++) {
            int e = lane + u * 32;
            int m = e >> 4, n = e & 15;
            int gcol = gcb + n;
            float val = patch[e];
            float* dst = (gcol < 512) ? (g_ypre + gcol * 16 + m)
                                      : (g_zpre + (gcol - 512) * 16 + m);
            atomicAdd(dst, val);
        }
        __syncwarp();
    }
#undef FC_ISSUE
}

// ---------------- small FC: outPre[n2][b] = bias[n2] + sum_k leaky(inPre[k][b]) w[k][n2]
template <int K>
__global__ void __launch_bounds__(128) smallfc_kernel(const float* __restrict__ inPre,
                                                      const float* __restrict__ w,
                                                      const float* __restrict__ bias,
                                                      float* __restrict__ outPre,
                                                      int N2) {
    __shared__ float xs[K * 16];
    int tid = threadIdx.x;
    for (int idx = tid; idx < K * 16; idx += 128) xs[idx] = leaky_f(inPre[idx]);
    __syncthreads();

    int n2 = blockIdx.x * 128 + tid;
    if (n2 < N2) {
        float acc[16];
#pragma unroll
        for (int b = 0; b < 16; b++) acc[b] = 0.f;
#pragma unroll 8
        for (int k = 0; k < K; k++) {
            float wv = __ldg(w + (size_t)k * N2 + n2);
#pragma unroll
            for (int b = 0; b < 16; b++) acc[b] = fmaf(wv, xs[k * 16 + b], acc[b]);
        }
        float bb = bias[n2];
#pragma unroll
        for (int b = 0; b < 16; b++) outPre[n2 * 16 + b] = acc[b] + bb;
    }
}

// ---------------- split-K small FC (128-row K slices), out pre-initialized with bias
__global__ void __launch_bounds__(128) splitfc_kernel(const float* __restrict__ inPre,
                                                      const float* __restrict__ w,
                                                      float* __restrict__ outAcc,
                                                      int N2) {
    __shared__ float xs[128 * 16];
    int tid = threadIdx.x;
    int kh = blockIdx.y;                    // k in [kh*128, kh*128+128)
    const float* ip = inPre + kh * 128 * 16;
    for (int idx = tid; idx < 128 * 16; idx += 128) xs[idx] = leaky_f(ip[idx]);
    __syncthreads();

    int n2 = blockIdx.x * 128 + tid;
    if (n2 < N2) {
        float acc[16];
#pragma unroll
        for (int b = 0; b < 16; b++) acc[b] = 0.f;
        const float* wp = w + (size_t)kh * 128 * N2 + n2;
#pragma unroll 8
        for (int k = 0; k < 128; k++) {
            float wv = __ldg(wp + (size_t)k * N2);
#pragma unroll
            for (int b = 0; b < 16; b++) acc[b] = fmaf(wv, xs[k * 16 + b], acc[b]);
        }
#pragma unroll
        for (int b = 0; b < 16; b++) atomicAdd(outAcc + n2 * 16 + b, acc[b]);
    }
}

// ---------------- fused z-chain: 256 ->128 ->128 ->64, one CTA ---------------
__global__ void __launch_bounds__(128) zfused_kernel(const float* __restrict__ w128a,
                                                     const float* __restrict__ b128a,
                                                     const float* __restrict__ w128b,
                                                     const float* __restrict__ b128b,
                                                     const float* __restrict__ w64,
                                                     const float* __restrict__ b64) {
    __shared__ float xa[256 * 16];
    __shared__ float xb[128 * 16];
    int tid = threadIdx.x;
    for (int idx = tid; idx < 256 * 16; idx += 128) xa[idx] = leaky_f(g_zpre[idx]);
    __syncthreads();

    {
        float acc[16];
#pragma unroll
        for (int b = 0; b < 16; b++) acc[b] = 0.f;
#pragma unroll 8
        for (int k = 0; k < 256; k++) {
            float wv = __ldg(w128a + (size_t)k * 128 + tid);
#pragma unroll
            for (int b = 0; b < 16; b++) acc[b] = fmaf(wv, xa[k * 16 + b], acc[b]);
        }
        float bb = b128a[tid];
#pragma unroll
        for (int b = 0; b < 16; b++) xb[tid * 16 + b] = leaky_f(acc[b] + bb);
    }
    __syncthreads();

    {
        float acc[16];
#pragma unroll
        for (int b = 0; b < 16; b++) acc[b] = 0.f;
#pragma unroll 8
        for (int k = 0; k < 128; k++) {
            float wv = __ldg(w128b + (size_t)k * 128 + tid);
#pragma unroll
            for (int b = 0; b < 16; b++) acc[b] = fmaf(wv, xb[k * 16 + b], acc[b]);
        }
        float bb = b128b[tid];
#pragma unroll
        for (int b = 0; b < 16; b++) xa[tid * 16 + b] = leaky_f(acc[b] + bb);
    }
    __syncthreads();

    if (tid < 64) {
        float acc[16];
#pragma unroll
        for (int b = 0; b < 16; b++) acc[b] = 0.f;
#pragma unroll 8
        for (int k = 0; k < 128; k++) {
            float wv = __ldg(w64 + (size_t)k * 64 + tid);
#pragma unroll
            for (int b = 0; b < 16; b++) acc[b] = fmaf(wv, xa[k * 16 + b], acc[b]);
        }
        float bb = b64[tid];
#pragma unroll
        for (int b = 0; b < 16; b++) g_z4[tid * 16 + b] = acc[b] + bb;
    }
}

// ---------------- heads: softmax(leaky(y3)@wsm+bsm), sigmoid(leaky(z5)@wsig+bsig)
__global__ void heads_kernel(const float* __restrict__ wsm, const float* __restrict__ bsm,
                             const float* __restrict__ wsig, const float* __restrict__ bsig,
                             float* __restrict__ out) {
    int idx = blockIdx.x * 256 + threadIdx.x;
    if (idx < 3600) {
        int b = idx / 225, p = idx % 225;
        float yv[13];
#pragma unroll
        for (int i = 0; i < 13; i++) yv[i] = leaky_f(g_y3[(p * 13 + i) * 16 + b]);
        float l[13];
        float m = -1e30f;
#pragma unroll
        for (int o = 0; o < 13; o++) {
            float s = bsm[o];
#pragma unroll
            for (int i = 0; i < 13; i++) s = fmaf(yv[i], wsm[i * 13 + o], s);
            l[o] = s;
            m = fmaxf(m, s);
        }
        float sum = 0.f;
#pragma unroll
        for (int o = 0; o < 13; o++) { l[o] = expf(l[o] - m); sum += l[o]; }
        float inv = 1.f / sum;
        float* dst = out + (size_t)(b * 225 + p) * 13;
#pragma unroll
        for (int o = 0; o < 13; o++) dst[o] = l[o] * inv;
    } else if (idx < 7200) {
        int j = idx - 3600;
        int b = j / 225, p = j % 225;
        float zv[4];
#pragma unroll
        for (int i = 0; i < 4; i++) zv[i] = leaky_f(g_z5[(p * 4 + i) * 16 + b]);
        float* dst = out + 46800 + (size_t)(b * 225 + p) * 4;
#pragma unroll
        for (int o = 0; o < 4; o++) {
            float s = bsig[o];
#pragma unroll
            for (int i = 0; i < 4; i++) s = fmaf(zv[i], wsig[i * 4 + o], s);
            dst[o] = 1.f / (1.f + expf(-s));
        }
    }
}

// ---------------- launch ----------------------------------------------------
extern "C" void kernel_launch(void* const* d_in, const int* in_sizes, int n_in,
                              void* d_out, int out_size) {
    const float* hidden  = (const float*)d_in[0];
    const float* conv1_w = (const float*)d_in[1];
    const float* conv1_b = (const float*)d_in[2];
    const float* conv2_w = (const float*)d_in[3];
    const float* conv2_b = (const float*)d_in[4];
    const float* w512    = (const float*)d_in[5];
    const float* b512    = (const float*)d_in[6];
    const float* w256a   = (const float*)d_in[7];
    const float* b256a   = (const float*)d_in[8];
    const float* wcls    = (const float*)d_in[9];
    const float* bcls    = (const float*)d_in[10];
    const float* wsm     = (const float*)d_in[11];
    const float* bsm     = (const float*)d_in[12];
    const float* w256b   = (const float*)d_in[13];
    const float* b256b   = (const float*)d_in[14];
    const float* w128a   = (const float*)d_in[15];
    const float* b128a   = (const float*)d_in[16];
    const float* w128b   = (const float*)d_in[17];
    const float* b128b   = (const float*)d_in[18];
    const float* w64     = (const float*)d_in[19];
    const float* b64     = (const float*)d_in[20];
    const float* wreg    = (const float*)d_in[21];
    const float* breg    = (const float*)d_in[22];
    const float* wsig    = (const float*)d_in[23];
    const float* bsig    = (const float*)d_in[24];
    float* out = (float*)d_out;

    float *ypre, *y2, *y3, *z4, *z5;
    cudaGetSymbolAddress((void**)&ypre, g_ypre);
    cudaGetSymbolAddress((void**)&y2, g_y2);
    cudaGetSymbolAddress((void**)&y3, g_y3);
    cudaGetSymbolAddress((void**)&z4, g_z4);
    cudaGetSymbolAddress((void**)&z5, g_z5);

    static bool attr_set = false;
    if (!attr_set) {
        cudaFuncSetAttribute(conv2_kernel, cudaFuncAttributeMaxDynamicSharedMemorySize, 54528);
        cudaFuncSetAttribute(fcbig_tf32_kernel, cudaFuncAttributeMaxDynamicSharedMemorySize, FC_SMEM_BYTES);
        attr_set = true;
    }

    prep_kernel<<<183, 256>>>(conv2_w, b512, b256b, bcls, b256a);
    conv1_kernel<<<dim3(P1H, BATCH), 256>>>(hidden, conv1_w, conv1_b);
    conv2_kernel<<<dim3(12, 24, BATCH), 256, 54528>>>(conv2_b);
    fcbig_tf32_kernel<<<NSLICES, 512, FC_SMEM_BYTES>>>(w512, w256b);

    splitfc_kernel<<<dim3(2, 4), 128>>>(ypre, w256a, y2, 256);
    splitfc_kernel<<<dim3(23, 2), 128>>>(y2, wcls, y3, 2925);
    zfused_kernel<<<1, 128>>>(w128a, b128a, w128b, b128b, w64, b64);
    smallfc_kernel<64><<<8, 128>>>(z4, wreg, breg, z5, 900);

    heads_kernel<<<29, 256>>>(wsm, bsm, wsig, bsig, out);
}

// round 13
// speedup vs baseline: 1.2752x; 1.1074x over previous
#include <cuda_runtime.h>
#include <cuda_bf16.h>
#include <mma.h>
#include <math.h>

using namespace nvcuda;

#define BATCH 16
#define P1H 97
#define P1W 383
#define C1 32
#define P2H 47
#define P2W 190
#define C2 64
#define FLAT 571520          // 47*190*64
#define KSLICE 640           // 893 * 640 = 571520 exactly
#define NSLICES 893
#define NCHUNK 80            // KSLICE / 8
#define FC_STAGES 3
#define FC_WLD 52                               // 48 cols + 4 pad floats per k-row
#define FC_STAGE_FLOATS (8 * FC_WLD)            // 416 floats per stage
#define FC_WARP_FLOATS (FC_STAGES * FC_STAGE_FLOATS)   // 1248
#define FC_SMEM_BYTES (16 * FC_WARP_FLOATS * 4)        // 79,872 B -> 2 CTAs/SM, ~68KB L1D left

// conv2 wide-tile geometry: 64 conv cols per CTA
#define CV2_APITCH 2112                          // 66 cols * 32 ch (halfs) per row
#define CV2_BPAD 72
#define CV2_SMEM_BYTES ((6 * CV2_APITCH + 288 * CV2_BPAD) * 2)   // 66,816 B

// ---------------- scratch (device globals; allocations are forbidden) -------
__device__ __align__(128) __nv_bfloat16 g_x1b[(size_t)BATCH * P1H * P1W * C1]; // conv1 out bf16
__device__ __align__(16)  __nv_bfloat16 g_w2b[288 * 64];                       // conv2 weights bf16
__device__ __align__(16)  float g_x2[(size_t)BATCH * FLAT];                    // conv2 out [b][k]
__device__ float g_ypre[512 * 16];   // [n][b]
__device__ float g_zpre[256 * 16];
__device__ float g_y2[256 * 16];
__device__ float g_y3[2925 * 16];
__device__ float g_z4[64 * 16];
__device__ float g_z5[900 * 16];

__device__ __forceinline__ float leaky_f(float x) { return x >= 0.f ? x : 0.01f * x; }

__device__ __forceinline__ unsigned long long pack2(float a, float b) {
    unsigned long long r;
    asm("mov.b64 %0, {%1, %2};" : "=l"(r) : "f"(a), "f"(b));
    return r;
}
__device__ __forceinline__ float2 unpack2(unsigned long long v) {
    float2 r;
    asm("mov.b64 {%0, %1}, %2;" : "=f"(r.x), "=f"(r.y) : "l"(v));
    return r;
}
__device__ __forceinline__ void ffma2(unsigned long long& acc, unsigned long long a, unsigned long long b) {
    asm("fma.rn.f32x2 %0, %1, %2, %0;" : "+l"(acc) : "l"(a), "l"(b));
}

// ---------------- prep: conv2 weight -> bf16 ; bias-init split-K accumulators
__global__ void prep_kernel(const float* __restrict__ w2,
                            const float* __restrict__ b512,
                            const float* __restrict__ b256b,
                            const float* __restrict__ bcls,
                            const float* __restrict__ b256a) {
    int i = blockIdx.x * 256 + threadIdx.x;
    if (i < 288 * 64) g_w2b[i] = __float2bfloat16(w2[i]);
    if (i < 512 * 16) g_ypre[i] = b512[i >> 4];
    if (i < 256 * 16) g_zpre[i] = b256b[i >> 4];
    if (i < 256 * 16) g_y2[i] = b256a[i >> 4];
    if (i < 2925 * 16) g_y3[i] = bcls[i >> 4];
}

// ---------------- conv1 (3x3, 1->32) + relu + maxpool2, fused, bf16 output --
// Channel pairs packed into fma.rn.f32x2 — half the FMA issue count.
__global__ void __launch_bounds__(256) conv1_kernel(const float* __restrict__ hidden,
                                                    const float* __restrict__ w1,
                                                    const float* __restrict__ b1) {
    __shared__ float ins[4 * 768];
    __shared__ float w1s[9 * 32];
    __shared__ float b1s[32];
    int b = blockIdx.y, ph = blockIdx.x;
    int tid = threadIdx.x;

    const float* src = hidden + ((size_t)b * 197 + 2 * ph) * 768;
    for (int i = tid; i < 4 * 768; i += 256) ins[i] = src[i];
    if (tid < 288) w1s[tid] = w1[tid];
    if (tid < 32) b1s[tid] = b1[tid];
    __syncthreads();

    int cg = tid >> 6;          // 0..3 (channel group of 8 = 4 pairs)
    int pwl = tid & 63;         // 0..63
    int c0 = cg * 8;

    unsigned long long wv2[9][4];
#pragma unroll
    for (int t = 0; t < 9; t++)
#pragma unroll
        for (int p = 0; p < 4; p++)
            wv2[t][p] = pack2(w1s[t * 32 + c0 + 2 * p], w1s[t * 32 + c0 + 2 * p + 1]);

    for (int it = 0; it < 6; it++) {
        int pw = it * 64 + pwl;
        if (pw >= 383) break;
        float in[4][4];
#pragma unroll
        for (int r = 0; r < 4; r++)
#pragma unroll
            for (int c = 0; c < 4; c++) in[r][c] = ins[r * 768 + 2 * pw + c];

        unsigned long long acc2[2][2][4];
#pragma unroll
        for (int i = 0; i < 2; i++)
#pragma unroll
            for (int j = 0; j < 2; j++)
#pragma unroll
                for (int p = 0; p < 4; p++) acc2[i][j][p] = 0ull;

#pragma unroll
        for (int t = 0; t < 9; t++) {
            int kh = t / 3, kw = t % 3;
#pragma unroll
            for (int i = 0; i < 2; i++)
#pragma unroll
                for (int j = 0; j < 2; j++) {
                    float x = in[i + kh][j + kw];
                    unsigned long long xx = pack2(x, x);
#pragma unroll
                    for (int p = 0; p < 4; p++)
                        ffma2(acc2[i][j][p], wv2[t][p], xx);
                }
        }

        size_t o = (((size_t)b * P1H + ph) * P1W + pw) * C1 + c0;
        __nv_bfloat162* dst = reinterpret_cast<__nv_bfloat162*>(g_x1b + o);
#pragma unroll
        for (int p = 0; p < 4; p++) {
            float2 a00 = unpack2(acc2[0][0][p]);
            float2 a01 = unpack2(acc2[0][1][p]);
            float2 a10 = unpack2(acc2[1][0][p]);
            float2 a11 = unpack2(acc2[1][1][p]);
            float m0 = fmaxf(fmaxf(a00.x, a01.x), fmaxf(a10.x, a11.x));
            float m1 = fmaxf(fmaxf(a00.y, a01.y), fmaxf(a10.y, a11.y));
            dst[p] = __floats2bfloat162_rn(fmaxf(m0 + b1s[c0 + 2 * p], 0.f),
                                           fmaxf(m1 + b1s[c0 + 2 * p + 1], 0.f));
        }
    }
}

// ---------------- conv2 (3x3, 32->64) bf16 wmma implicit GEMM + relu + pool --
// WIDE tiles: 64 conv cols per CTA (grid.x = 6). Each warp: (conv-row 0..3,
// 32-col half) = 2 m-tiles x 4 n-tiles; B fragment reused across both m-tiles.
__global__ void __launch_bounds__(256, 2) conv2_kernel(const float* __restrict__ b2) {
    extern __shared__ __align__(16) __nv_bfloat16 smem_h[];
    __nv_bfloat16* x1s = smem_h;                     // 6*2112 halfs = 25,344 B
    __nv_bfloat16* w2s = smem_h + 6 * CV2_APITCH;    // 288*72 halfs = 41,472 B

    int wt = blockIdx.x;        // 0..5
    int pb = blockIdx.y;        // 0..23
    int b = blockIdx.z;         // 0..15
    int tid = threadIdx.x;
    int h0 = 4 * pb;
    int w0 = wt * 64;

    // stage A: 6 rows x 264 uint4 (66 cols x 32ch); border-clamped (clamped
    // data only feeds discarded outputs)
    for (int i = tid; i < 6 * 264; i += 256) {
        int r = i / 264, q = i - r * 264;
        int row = h0 + r; if (row > 96) row = 96;
        int col = w0 + (q >> 2); if (col > 382) col = 382;
        const uint4 v = *(const uint4*)(g_x1b + (((size_t)b * P1H + row) * P1W + col) * C1 + (q & 3) * 8);
        *(uint4*)(x1s + (size_t)r * CV2_APITCH + q * 8) = v;
    }
    // stage B with row padding 64->72: 288 rows x 8 uint4
    for (int i = tid; i < 2304; i += 256) {
        int k = i >> 3, n0 = (i & 7) * 8;
        uint4 v = *(const uint4*)(g_w2b + k * 64 + n0);
        *(uint4*)(w2s + k * CV2_BPAD + n0) = v;
    }
    __syncthreads();

    int wid = tid >> 5;
    int rloc = wid >> 1;            // conv-row offset 0..3
    int hOff = (wid & 1) * 32;      // 32-col half

    wmma::fragment<wmma::matrix_a, 16, 16, 16, __nv_bfloat16, wmma::row_major> af[2];
    wmma::fragment<wmma::matrix_b, 16, 16, 16, __nv_bfloat16, wmma::row_major> bf;
    wmma::fragment<wmma::accumulator, 16, 16, 16, float> acc[2][4];
#pragma unroll
    for (int mt = 0; mt < 2; mt++)
#pragma unroll
        for (int nf = 0; nf < 4; nf++) wmma::fill_fragment(acc[mt][nf], 0.f);

#pragma unroll
    for (int kh = 0; kh < 3; kh++) {
        const __nv_bfloat16* base = x1s + (rloc + kh) * CV2_APITCH + hOff * 32;
#pragma unroll
        for (int jc = 0; jc < 6; jc++) {
            wmma::load_matrix_sync(af[0], base + jc * 16, 32);
            wmma::load_matrix_sync(af[1], base + 512 + jc * 16, 32);   // +16 cols
            const __nv_bfloat16* bp = w2s + (kh * 96 + jc * 16) * CV2_BPAD;
#pragma unroll
            for (int nf = 0; nf < 4; nf++) {
                wmma::load_matrix_sync(bf, bp + nf * 16, CV2_BPAD);
                wmma::mma_sync(acc[0][nf], af[0], bf, acc[0][nf]);
                wmma::mma_sync(acc[1][nf], af[1], bf, acc[1][nf]);
            }
        }
    }

    __syncthreads();                 // staging fully consumed -> reuse as C
    float* cs = reinterpret_cast<float*>(smem_h);    // 16 tiles x 1024 floats = 64KB <= 66.8KB
#pragma unroll
    for (int mt = 0; mt < 2; mt++)
#pragma unroll
        for (int nf = 0; nf < 4; nf++)
            wmma::store_matrix_sync(cs + (wid * 2 + mt) * 1024 + nf * 16, acc[mt][nf],
                                    64, wmma::mem_row_major);
    __syncthreads();

    // pooling epilogue: 2 iterations; idx -> (pr 0..1, pj 0..31, 8 channels)
#pragma unroll
    for (int it = 0; it < 2; it++) {
        int idx = it * 256 + tid;           // 0..511
        int pr = idx >> 8;
        int pj = (idx >> 3) & 31;
        int c0 = (idx & 7) * 8;
        int ph2 = 2 * pb + pr;
        int pwg = wt * 32 + pj;
        if (ph2 < P2H && pwg < P2W) {
            float v[8];
#pragma unroll
            for (int cc = 0; cc < 8; cc++) {
                int c = c0 + cc;
                float m = -1e30f;
#pragma unroll
                for (int i = 0; i < 2; i++)
#pragma unroll
                    for (int j = 0; j < 2; j++) {
                        int rr = 2 * pr + i;          // conv row 0..3
                        int jj = 2 * pj + j;          // conv col 0..63
                        m = fmaxf(m, cs[((rr * 2 + (jj >> 5)) * 2 + ((jj >> 4) & 1)) * 1024
                                        + (jj & 15) * 64 + c]);
                    }
                v[cc] = fmaxf(m + b2[c], 0.f);
            }
            size_t o = (size_t)b * FLAT + ((size_t)ph2 * P2W + pwg) * C2 + c0;
            float4 o0 = {v[0], v[1], v[2], v[3]};
            float4 o1 = {v[4], v[5], v[6], v[7]};
            *reinterpret_cast<float4*>(g_x2 + o) = o0;
            *reinterpret_cast<float4*>(g_x2 + o + 4) = o1;
        }
    }
}

// ---------------- big FC via TF32 tensor cores, warp-private cp.async rings --
// [R9-verbatim: best measured 342us — FROZEN]
__global__ void __launch_bounds__(512, 2) fcbig_tf32_kernel(const float* __restrict__ w512,
                                                            const float* __restrict__ w256b) {
    extern __shared__ __align__(16) float ws[];  // [16 warps][3 stages][8][FC_WLD]

    int tid = threadIdx.x;
    int wid = tid >> 5;
    int lane = tid & 31;
    size_t k0 = (size_t)blockIdx.x * KSLICE;

    const float* gsrc[3];
    int gstep[3];
    unsigned soff[3];
#pragma unroll
    for (int i = 0; i < 3; i++) {
        int idx = lane + i * 32;              // 0..95
        int r = idx / 12;
        int c4 = idx - r * 12;
        int gcol = wid * 48 + c4 * 4;
        if (gcol < 512) { gsrc[i] = w512  + (k0 + r) * 512 + gcol;         gstep[i] = 8 * 512; }
        else            { gsrc[i] = w256b + (k0 + r) * 256 + (gcol - 512); gstep[i] = 8 * 256; }
        soff[i] = (unsigned)((r * FC_WLD + c4 * 4) * 4);
    }
    unsigned wbase = (unsigned)__cvta_generic_to_shared(ws) + wid * (FC_WARP_FLOATS * 4);

#define FC_ISSUE(c)                                                               \
    {                                                                             \
        unsigned sb = wbase + ((c) % FC_STAGES) * (FC_STAGE_FLOATS * 4);          \
        _Pragma("unroll")                                                         \
        for (int i = 0; i < 3; i++) {                                             \
            const float* g = gsrc[i] + (size_t)(c) * gstep[i];                    \
            asm volatile("cp.async.cg.shared.global [%0], [%1], 16;"              \
                         :: "r"(sb + soff[i]), "l"(g));                           \
        }                                                                         \
        asm volatile("cp.async.commit_group;");                                   \
    }

    FC_ISSUE(0); FC_ISSUE(1);

    wmma::fragment<wmma::matrix_a, 16, 16, 8, wmma::precision::tf32, wmma::row_major> af;
    wmma::fragment<wmma::matrix_b, 16, 16, 8, wmma::precision::tf32, wmma::row_major> bfr;
    wmma::fragment<wmma::accumulator, 16, 16, 8, float> acc[3];
#pragma unroll
    for (int t = 0; t < 3; t++) wmma::fill_fragment(acc[t], 0.f);

    const float* wsw = ws + wid * FC_WARP_FLOATS;
    const float* abase = g_x2 + k0;              // A[m][kk] = abase[m*FLAT + c*8 + kk]
    for (int c = 0; c < NCHUNK; c++) {
        asm volatile("cp.async.wait_group 1;");
        __syncwarp();

        wmma::load_matrix_sync(af, abase + c * 8, FLAT);   // gmem, L1-shared
        const float* buf = wsw + (c % FC_STAGES) * FC_STAGE_FLOATS;
#pragma unroll
        for (int t = 0; t < 3; t++) {
            wmma::load_matrix_sync(bfr, buf + t * 16, FC_WLD);
            wmma::mma_sync(acc[t], af, bfr, acc[t]);
        }

        if (c + 2 < NCHUNK) FC_ISSUE(c + 2);
    }
    asm volatile("cp.async.wait_group 0;");
    __syncwarp();

    float* patch = ws + wid * FC_WARP_FLOATS;
#pragma unroll
    for (int t = 0; t < 3; t++) {
        wmma::store_matrix_sync(patch, acc[t], 16, wmma::mem_row_major);
        __syncwarp();
        int gcb = wid * 48 + t * 16;
#pragma unroll
        for (int u = 0; u < 8; u++) {
            int e = lane + u * 32;
            int m = e >> 4, n = e & 15;
            int gcol = gcb + n;
            float val = patch[e];
            float* dst = (gcol < 512) ? (g_ypre + gcol * 16 + m)
                                      : (g_zpre + (gcol - 512) * 16 + m);
            atomicAdd(dst, val);
        }
        __syncwarp();
    }
#undef FC_ISSUE
}

// ---------------- tail1: {split-K y2 (8 CTAs)} || {fused z-chain (1 CTA)} ----
// Both depend only on fcbig. g_y2 bias-pre-initialized in prep.
__global__ void __launch_bounds__(128) tail1_kernel(const float* __restrict__ w256a,
                                                    const float* __restrict__ w128a,
                                                    const float* __restrict__ b128a,
                                                    const float* __restrict__ w128b,
                                                    const float* __restrict__ b128b,
                                                    const float* __restrict__ w64,
                                                    const float* __restrict__ b64) {
    __shared__ float xs[384 * 16];   // 24 KB, used differently per branch
    int tid = threadIdx.x;

    if (blockIdx.x < 8) {
        // split-K y2: nb = n-tile (0..1), kh = K slice (0..3) of ypre[512]
        int nb = blockIdx.x & 1, kh = blockIdx.x >> 1;
        const float* ip = g_ypre + kh * 128 * 16;
        for (int idx = tid; idx < 128 * 16; idx += 128) xs[idx] = leaky_f(ip[idx]);
        __syncthreads();

        int n2 = nb * 128 + tid;
        float acc[16];
#pragma unroll
        for (int b = 0; b < 16; b++) acc[b] = 0.f;
        const float* wp = w256a + (size_t)kh * 128 * 256 + n2;
#pragma unroll 8
        for (int k = 0; k < 128; k++) {
            float wv = __ldg(wp + (size_t)k * 256);
#pragma unroll
            for (int b = 0; b < 16; b++) acc[b] = fmaf(wv, xs[k * 16 + b], acc[b]);
        }
#pragma unroll
        for (int b = 0; b < 16; b++) atomicAdd(g_y2 + n2 * 16 + b, acc[b]);
    } else {
        // fused z-chain: 256 -> 128 -> 128 -> 64
        float* xa = xs;              // 256*16
        float* xb = xs + 256 * 16;   // 128*16
        for (int idx = tid; idx < 256 * 16; idx += 128) xa[idx] = leaky_f(g_zpre[idx]);
        __syncthreads();

        {
            float acc[16];
#pragma unroll
            for (int b = 0; b < 16; b++) acc[b] = 0.f;
#pragma unroll 8
            for (int k = 0; k < 256; k++) {
                float wv = __ldg(w128a + (size_t)k * 128 + tid);
#pragma unroll
                for (int b = 0; b < 16; b++) acc[b] = fmaf(wv, xa[k * 16 + b], acc[b]);
            }
            float bb = b128a[tid];
#pragma unroll
            for (int b = 0; b < 16; b++) xb[tid * 16 + b] = leaky_f(acc[b] + bb);
        }
        __syncthreads();

        {
            float acc[16];
#pragma unroll
            for (int b = 0; b < 16; b++) acc[b] = 0.f;
#pragma unroll 8
            for (int k = 0; k < 128; k++) {
                float wv = __ldg(w128b + (size_t)k * 128 + tid);
#pragma unroll
                for (int b = 0; b < 16; b++) acc[b] = fmaf(wv, xb[k * 16 + b], acc[b]);
            }
            float bb = b128b[tid];
#pragma unroll
            for (int b = 0; b < 16; b++) xa[tid * 16 + b] = leaky_f(acc[b] + bb);
        }
        __syncthreads();

        if (tid < 64) {
            float acc[16];
#pragma unroll
            for (int b = 0; b < 16; b++) acc[b] = 0.f;
#pragma unroll 8
            for (int k = 0; k < 128; k++) {
                float wv = __ldg(w64 + (size_t)k * 64 + tid);
#pragma unroll
                for (int b = 0; b < 16; b++) acc[b] = fmaf(wv, xa[k * 16 + b], acc[b]);
            }
            float bb = b64[tid];
#pragma unroll
            for (int b = 0; b < 16; b++) g_z4[tid * 16 + b] = acc[b] + bb;
        }
    }
}

// ---------------- tail2: {split-K y3 (46 CTAs)} || {z5 FC (8 CTAs)} ---------
__global__ void __launch_bounds__(128) tail2_kernel(const float* __restrict__ wcls,
                                                    const float* __restrict__ wreg,
                                                    const float* __restrict__ breg) {
    __shared__ float xs[128 * 16];
    int tid = threadIdx.x;

    if (blockIdx.x < 46) {
        // split-K y3: g_y2[256] -> g_y3[2925] (bias pre-initialized)
        int nb = blockIdx.x % 23, kh = blockIdx.x / 23;
        const float* ip = g_y2 + kh * 128 * 16;
        for (int idx = tid; idx < 128 * 16; idx += 128) xs[idx] = leaky_f(ip[idx]);
        __syncthreads();

        int n2 = nb * 128 + tid;
        if (n2 < 2925) {
            float acc[16];
#pragma unroll
            for (int b = 0; b < 16; b++) acc[b] = 0.f;
            const float* wp = wcls + (size_t)kh * 128 * 2925 + n2;
#pragma unroll 8
            for (int k = 0; k < 128; k++) {
                float wv = __ldg(wp + (size_t)k * 2925);
#pragma unroll
                for (int b = 0; b < 16; b++) acc[b] = fmaf(wv, xs[k * 16 + b], acc[b]);
            }
#pragma unroll
            for (int b = 0; b < 16; b++) atomicAdd(g_y3 + n2 * 16 + b, acc[b]);
        }
    } else {
        // z5 FC: g_z4[64] -> g_z5[900]
        int bx = blockIdx.x - 46;
        for (int idx = tid; idx < 64 * 16; idx += 128) xs[idx] = leaky_f(g_z4[idx]);
        __syncthreads();

        int n2 = bx * 128 + tid;
        if (n2 < 900) {
            float acc[16];
#pragma unroll
            for (int b = 0; b < 16; b++) acc[b] = 0.f;
#pragma unroll 8
            for (int k = 0; k < 64; k++) {
                float wv = __ldg(wreg + (size_t)k * 900 + n2);
#pragma unroll
                for (int b = 0; b < 16; b++) acc[b] = fmaf(wv, xs[k * 16 + b], acc[b]);
            }
            float bb = breg[n2];
#pragma unroll
            for (int b = 0; b < 16; b++) g_z5[n2 * 16 + b] = acc[b] + bb;
        }
    }
}

// ---------------- heads: softmax(leaky(y3)@wsm+bsm), sigmoid(leaky(z5)@wsig+bsig)
__global__ void heads_kernel(const float* __restrict__ wsm, const float* __restrict__ bsm,
                             const float* __restrict__ wsig, const float* __restrict__ bsig,
                             float* __restrict__ out) {
    int idx = blockIdx.x * 256 + threadIdx.x;
    if (idx < 3600) {
        int b = idx / 225, p = idx % 225;
        float yv[13];
#pragma unroll
        for (int i = 0; i < 13; i++) yv[i] = leaky_f(g_y3[(p * 13 + i) * 16 + b]);
        float l[13];
        float m = -1e30f;
#pragma unroll
        for (int o = 0; o < 13; o++) {
            float s = bsm[o];
#pragma unroll
            for (int i = 0; i < 13; i++) s = fmaf(yv[i], wsm[i * 13 + o], s);
            l[o] = s;
            m = fmaxf(m, s);
        }
        float sum = 0.f;
#pragma unroll
        for (int o = 0; o < 13; o++) { l[o] = expf(l[o] - m); sum += l[o]; }
        float inv = 1.f / sum;
        float* dst = out + (size_t)(b * 225 + p) * 13;
#pragma unroll
        for (int o = 0; o < 13; o++) dst[o] = l[o] * inv;
    } else if (idx < 7200) {
        int j = idx - 3600;
        int b = j / 225, p = j % 225;
        float zv[4];
#pragma unroll
        for (int i = 0; i < 4; i++) zv[i] = leaky_f(g_z5[(p * 4 + i) * 16 + b]);
        float* dst = out + 46800 + (size_t)(b * 225 + p) * 4;
#pragma unroll
        for (int o = 0; o < 4; o++) {
            float s = bsig[o];
#pragma unroll
            for (int i = 0; i < 4; i++) s = fmaf(zv[i], wsig[i * 4 + o], s);
            dst[o] = 1.f / (1.f + expf(-s));
        }
    }
}

// ---------------- launch ----------------------------------------------------
extern "C" void kernel_launch(void* const* d_in, const int* in_sizes, int n_in,
                              void* d_out, int out_size) {
    const float* hidden  = (const float*)d_in[0];
    const float* conv1_w = (const float*)d_in[1];
    const float* conv1_b = (const float*)d_in[2];
    const float* conv2_w = (const float*)d_in[3];
    const float* conv2_b = (const float*)d_in[4];
    const float* w512    = (const float*)d_in[5];
    const float* b512    = (const float*)d_in[6];
    const float* w256a   = (const float*)d_in[7];
    const float* b256a   = (const float*)d_in[8];
    const float* wcls    = (const float*)d_in[9];
    const float* bcls    = (const float*)d_in[10];
    const float* wsm     = (const float*)d_in[11];
    const float* bsm     = (const float*)d_in[12];
    const float* w256b   = (const float*)d_in[13];
    const float* b256b   = (const float*)d_in[14];
    const float* w128a   = (const float*)d_in[15];
    const float* b128a   = (const float*)d_in[16];
    const float* w128b   = (const float*)d_in[17];
    const float* b128b   = (const float*)d_in[18];
    const float* w64     = (const float*)d_in[19];
    const float* b64     = (const float*)d_in[20];
    const float* wreg    = (const float*)d_in[21];
    const float* breg    = (const float*)d_in[22];
    const float* wsig    = (const float*)d_in[23];
    const float* bsig    = (const float*)d_in[24];
    float* out = (float*)d_out;

    static bool attr_set = false;
    if (!attr_set) {
        cudaFuncSetAttribute(conv2_kernel, cudaFuncAttributeMaxDynamicSharedMemorySize, CV2_SMEM_BYTES);
        cudaFuncSetAttribute(fcbig_tf32_kernel, cudaFuncAttributeMaxDynamicSharedMemorySize, FC_SMEM_BYTES);
        attr_set = true;
    }

    prep_kernel<<<183, 256>>>(conv2_w, b512, b256b, bcls, b256a);
    conv1_kernel<<<dim3(P1H, BATCH), 256>>>(hidden, conv1_w, conv1_b);
    conv2_kernel<<<dim3(6, 24, BATCH), 256, CV2_SMEM_BYTES>>>(conv2_b);
    fcbig_tf32_kernel<<<NSLICES, 512, FC_SMEM_BYTES>>>(w512, w256b);

    tail1_kernel<<<9, 128>>>(w256a, w128a, b128a, w128b, b128b, w64, b64);
    tail2_kernel<<<54, 128>>>(wcls, wreg, breg);

    heads_kernel<<<29, 256>>>(wsm, bsm, wsig, bsig, out);
}

// round 14
// speedup vs baseline: 1.4381x; 1.1277x over previous
#include <cuda_runtime.h>
#include <cuda_bf16.h>
#include <mma.h>
#include <math.h>

using namespace nvcuda;

#define BATCH 16
#define P1H 97
#define P1W 383
#define C1 32
#define P2H 47
#define P2W 190
#define C2 64
#define FLAT 571520          // 47*190*64
#define KSLICE 640           // 893 * 640 = 571520 exactly
#define NSLICES 893
#define NCHUNK 80            // KSLICE / 8
#define FC_STAGES 3
#define FC_WLD 52                               // 48 cols + 4 pad floats per k-row
#define FC_STAGE_FLOATS (8 * FC_WLD)            // 416 floats per stage
#define FC_WARP_FLOATS (FC_STAGES * FC_STAGE_FLOATS)   // 1248
#define FC_SMEM_BYTES (16 * FC_WARP_FLOATS * 4)        // 79,872 B -> 2 CTAs/SM

// conv2 wide-tile geometry: 64 conv cols per CTA
#define CV2_APITCH 2112                          // 66 cols * 32 ch (halfs) per row
#define CV2_BPAD 72
#define CV2_SMEM_BYTES ((6 * CV2_APITCH + 288 * CV2_BPAD) * 2)   // 66,816 B

// ---------------- scratch (device globals; allocations are forbidden) -------
__device__ __align__(128) __nv_bfloat16 g_x1b[(size_t)BATCH * P1H * P1W * C1]; // conv1 out bf16
__device__ __align__(16)  __nv_bfloat16 g_w2b[288 * 64];                       // conv2 weights bf16
__device__ __align__(16)  float g_x2[(size_t)BATCH * FLAT];                    // conv2 out [b][k]
__device__ __align__(128) float g_x2t[(size_t)FLAT * 16];                      // transposed [k][b]
__device__ float g_ypre[512 * 16];   // [n][b]
__device__ float g_zpre[256 * 16];
__device__ float g_y2[256 * 16];
__device__ float g_y3[2925 * 16];
__device__ float g_z4[64 * 16];
__device__ float g_z5[900 * 16];

__device__ __forceinline__ float leaky_f(float x) { return x >= 0.f ? x : 0.01f * x; }

__device__ __forceinline__ unsigned long long pack2(float a, float b) {
    unsigned long long r;
    asm("mov.b64 %0, {%1, %2};" : "=l"(r) : "f"(a), "f"(b));
    return r;
}
__device__ __forceinline__ float2 unpack2(unsigned long long v) {
    float2 r;
    asm("mov.b64 {%0, %1}, %2;" : "=f"(r.x), "=f"(r.y) : "l"(v));
    return r;
}
__device__ __forceinline__ void ffma2(unsigned long long& acc, unsigned long long a, unsigned long long b) {
    asm("fma.rn.f32x2 %0, %1, %2, %0;" : "+l"(acc) : "l"(a), "l"(b));
}

// raw tf32 mma m16n8k8 (documented fragment layout; acc in place)
__device__ __forceinline__ void mma_tf32(float (&d)[4],
                                         unsigned a0, unsigned a1, unsigned a2, unsigned a3,
                                         unsigned b0, unsigned b1) {
    asm volatile(
        "mma.sync.aligned.m16n8k8.row.col.f32.tf32.tf32.f32 "
        "{%0,%1,%2,%3},{%4,%5,%6,%7},{%8,%9},{%0,%1,%2,%3};"
        : "+f"(d[0]), "+f"(d[1]), "+f"(d[2]), "+f"(d[3])
        : "r"(a0), "r"(a1), "r"(a2), "r"(a3), "r"(b0), "r"(b1));
}

// ---------------- prep: conv2 weight -> bf16 ; bias-init split-K accumulators
__global__ void prep_kernel(const float* __restrict__ w2,
                            const float* __restrict__ b512,
                            const float* __restrict__ b256b,
                            const float* __restrict__ bcls,
                            const float* __restrict__ b256a) {
    int i = blockIdx.x * 256 + threadIdx.x;
    if (i < 288 * 64) g_w2b[i] = __float2bfloat16(w2[i]);
    if (i < 512 * 16) g_ypre[i] = b512[i >> 4];
    if (i < 256 * 16) g_zpre[i] = b256b[i >> 4];
    if (i < 256 * 16) g_y2[i] = b256a[i >> 4];
    if (i < 2925 * 16) g_y3[i] = bcls[i >> 4];
}

// ---------------- conv1 (3x3, 1->32) + relu + maxpool2, fused, bf16 output --
__global__ void __launch_bounds__(256) conv1_kernel(const float* __restrict__ hidden,
                                                    const float* __restrict__ w1,
                                                    const float* __restrict__ b1) {
    __shared__ float ins[4 * 768];
    __shared__ float w1s[9 * 32];
    __shared__ float b1s[32];
    int b = blockIdx.y, ph = blockIdx.x;
    int tid = threadIdx.x;

    const float* src = hidden + ((size_t)b * 197 + 2 * ph) * 768;
    for (int i = tid; i < 4 * 768; i += 256) ins[i] = src[i];
    if (tid < 288) w1s[tid] = w1[tid];
    if (tid < 32) b1s[tid] = b1[tid];
    __syncthreads();

    int cg = tid >> 6;
    int pwl = tid & 63;
    int c0 = cg * 8;

    unsigned long long wv2[9][4];
#pragma unroll
    for (int t = 0; t < 9; t++)
#pragma unroll
        for (int p = 0; p < 4; p++)
            wv2[t][p] = pack2(w1s[t * 32 + c0 + 2 * p], w1s[t * 32 + c0 + 2 * p + 1]);

    for (int it = 0; it < 6; it++) {
        int pw = it * 64 + pwl;
        if (pw >= 383) break;
        float in[4][4];
#pragma unroll
        for (int r = 0; r < 4; r++)
#pragma unroll
            for (int c = 0; c < 4; c++) in[r][c] = ins[r * 768 + 2 * pw + c];

        unsigned long long acc2[2][2][4];
#pragma unroll
        for (int i = 0; i < 2; i++)
#pragma unroll
            for (int j = 0; j < 2; j++)
#pragma unroll
                for (int p = 0; p < 4; p++) acc2[i][j][p] = 0ull;

#pragma unroll
        for (int t = 0; t < 9; t++) {
            int kh = t / 3, kw = t % 3;
#pragma unroll
            for (int i = 0; i < 2; i++)
#pragma unroll
                for (int j = 0; j < 2; j++) {
                    float x = in[i + kh][j + kw];
                    unsigned long long xx = pack2(x, x);
#pragma unroll
                    for (int p = 0; p < 4; p++)
                        ffma2(acc2[i][j][p], wv2[t][p], xx);
                }
        }

        size_t o = (((size_t)b * P1H + ph) * P1W + pw) * C1 + c0;
        __nv_bfloat162* dst = reinterpret_cast<__nv_bfloat162*>(g_x1b + o);
#pragma unroll
        for (int p = 0; p < 4; p++) {
            float2 a00 = unpack2(acc2[0][0][p]);
            float2 a01 = unpack2(acc2[0][1][p]);
            float2 a10 = unpack2(acc2[1][0][p]);
            float2 a11 = unpack2(acc2[1][1][p]);
            float m0 = fmaxf(fmaxf(a00.x, a01.x), fmaxf(a10.x, a11.x));
            float m1 = fmaxf(fmaxf(a00.y, a01.y), fmaxf(a10.y, a11.y));
            dst[p] = __floats2bfloat162_rn(fmaxf(m0 + b1s[c0 + 2 * p], 0.f),
                                           fmaxf(m1 + b1s[c0 + 2 * p + 1], 0.f));
        }
    }
}

// ---------------- conv2 (3x3, 32->64) bf16 wmma implicit GEMM + relu + pool --
__global__ void __launch_bounds__(256, 2) conv2_kernel(const float* __restrict__ b2) {
    extern __shared__ __align__(16) __nv_bfloat16 smem_h[];
    __nv_bfloat16* x1s = smem_h;
    __nv_bfloat16* w2s = smem_h + 6 * CV2_APITCH;

    int wt = blockIdx.x;        // 0..5
    int pb = blockIdx.y;        // 0..23
    int b = blockIdx.z;         // 0..15
    int tid = threadIdx.x;
    int h0 = 4 * pb;
    int w0 = wt * 64;

    for (int i = tid; i < 6 * 264; i += 256) {
        int r = i / 264, q = i - r * 264;
        int row = h0 + r; if (row > 96) row = 96;
        int col = w0 + (q >> 2); if (col > 382) col = 382;
        const uint4 v = *(const uint4*)(g_x1b + (((size_t)b * P1H + row) * P1W + col) * C1 + (q & 3) * 8);
        *(uint4*)(x1s + (size_t)r * CV2_APITCH + q * 8) = v;
    }
    for (int i = tid; i < 2304; i += 256) {
        int k = i >> 3, n0 = (i & 7) * 8;
        uint4 v = *(const uint4*)(g_w2b + k * 64 + n0);
        *(uint4*)(w2s + k * CV2_BPAD + n0) = v;
    }
    __syncthreads();

    int wid = tid >> 5;
    int rloc = wid >> 1;
    int hOff = (wid & 1) * 32;

    wmma::fragment<wmma::matrix_a, 16, 16, 16, __nv_bfloat16, wmma::row_major> af[2];
    wmma::fragment<wmma::matrix_b, 16, 16, 16, __nv_bfloat16, wmma::row_major> bf;
    wmma::fragment<wmma::accumulator, 16, 16, 16, float> acc[2][4];
#pragma unroll
    for (int mt = 0; mt < 2; mt++)
#pragma unroll
        for (int nf = 0; nf < 4; nf++) wmma::fill_fragment(acc[mt][nf], 0.f);

#pragma unroll
    for (int kh = 0; kh < 3; kh++) {
        const __nv_bfloat16* base = x1s + (rloc + kh) * CV2_APITCH + hOff * 32;
#pragma unroll
        for (int jc = 0; jc < 6; jc++) {
            wmma::load_matrix_sync(af[0], base + jc * 16, 32);
            wmma::load_matrix_sync(af[1], base + 512 + jc * 16, 32);
            const __nv_bfloat16* bp = w2s + (kh * 96 + jc * 16) * CV2_BPAD;
#pragma unroll
            for (int nf = 0; nf < 4; nf++) {
                wmma::load_matrix_sync(bf, bp + nf * 16, CV2_BPAD);
                wmma::mma_sync(acc[0][nf], af[0], bf, acc[0][nf]);
                wmma::mma_sync(acc[1][nf], af[1], bf, acc[1][nf]);
            }
        }
    }

    __syncthreads();
    float* cs = reinterpret_cast<float*>(smem_h);
#pragma unroll
    for (int mt = 0; mt < 2; mt++)
#pragma unroll
        for (int nf = 0; nf < 4; nf++)
            wmma::store_matrix_sync(cs + (wid * 2 + mt) * 1024 + nf * 16, acc[mt][nf],
                                    64, wmma::mem_row_major);
    __syncthreads();

#pragma unroll
    for (int it = 0; it < 2; it++) {
        int idx = it * 256 + tid;
        int pr = idx >> 8;
        int pj = (idx >> 3) & 31;
        int c0 = (idx & 7) * 8;
        int ph2 = 2 * pb + pr;
        int pwg = wt * 32 + pj;
        if (ph2 < P2H && pwg < P2W) {
            float v[8];
#pragma unroll
            for (int cc = 0; cc < 8; cc++) {
                int c = c0 + cc;
                float m = -1e30f;
#pragma unroll
                for (int i = 0; i < 2; i++)
#pragma unroll
                    for (int j = 0; j < 2; j++) {
                        int rr = 2 * pr + i;
                        int jj = 2 * pj + j;
                        m = fmaxf(m, cs[((rr * 2 + (jj >> 5)) * 2 + ((jj >> 4) & 1)) * 1024
                                        + (jj & 15) * 64 + c]);
                    }
                v[cc] = fmaxf(m + b2[c], 0.f);
            }
            size_t o = (size_t)b * FLAT + ((size_t)ph2 * P2W + pwg) * C2 + c0;
            float4 o0 = {v[0], v[1], v[2], v[3]};
            float4 o1 = {v[4], v[5], v[6], v[7]};
            *reinterpret_cast<float4*>(g_x2 + o) = o0;
            *reinterpret_cast<float4*>(g_x2 + o + 4) = o1;
        }
    }
}

// ---------------- transpose x2[b][k] -> x2t[k][b], coalesced both sides -----
__global__ void __launch_bounds__(256) xpose_kernel() {
    __shared__ float s[640 * 17];
    size_t k0 = (size_t)blockIdx.x * 640;
    int tid = threadIdx.x;
    for (int idx = tid; idx < 640 * 16; idx += 256) {
        int b = idx / 640, kk = idx - b * 640;
        s[kk * 17 + b] = g_x2[(size_t)b * FLAT + k0 + kk];
    }
    __syncthreads();
    for (int idx = tid; idx < 640 * 16; idx += 256) {
        int k = idx >> 4, bb = idx & 15;
        g_x2t[(k0 + k) * 16 + bb] = s[k * 17 + bb];
    }
}

// ---------------- big FC via raw tf32 mma.sync, warp-private cp.async rings --
// D[16, 768] += x[16, K] @ (w512 | w256b), split-K over 893 slices.
// Ring/cp.async identical to frozen R9 config. A tiles: contiguous 512B blocks
// of x2t (2 L1 lines/chunk shared by all warps). B: conflict-free LDS.32 from
// the k-major [8][52] ring. Epilogue: direct per-register atomicAdd.
__global__ void __launch_bounds__(512, 2) fcbig_tf32_kernel(const float* __restrict__ w512,
                                                            const float* __restrict__ w256b) {
    extern __shared__ __align__(16) float ws[];  // [16 warps][3 stages][8][FC_WLD]

    int tid = threadIdx.x;
    int wid = tid >> 5;
    int lane = tid & 31;
    int g = lane >> 2;        // groupID 0..7
    int tig = lane & 3;       // thread-in-group 0..3
    size_t k0 = (size_t)blockIdx.x * KSLICE;

    // per-thread cp.async precompute (unchanged from frozen config)
    const float* gsrc[3];
    int gstep[3];
    unsigned soff[3];
#pragma unroll
    for (int i = 0; i < 3; i++) {
        int idx = lane + i * 32;
        int r = idx / 12;
        int c4 = idx - r * 12;
        int gcol = wid * 48 + c4 * 4;
        if (gcol < 512) { gsrc[i] = w512  + (k0 + r) * 512 + gcol;         gstep[i] = 8 * 512; }
        else            { gsrc[i] = w256b + (k0 + r) * 256 + (gcol - 512); gstep[i] = 8 * 256; }
        soff[i] = (unsigned)((r * FC_WLD + c4 * 4) * 4);
    }
    unsigned wbase = (unsigned)__cvta_generic_to_shared(ws) + wid * (FC_WARP_FLOATS * 4);

#define FC_ISSUE(c)                                                               \
    {                                                                             \
        unsigned sb = wbase + ((c) % FC_STAGES) * (FC_STAGE_FLOATS * 4);          \
        _Pragma("unroll")                                                         \
        for (int i = 0; i < 3; i++) {                                             \
            const float* gp = gsrc[i] + (size_t)(c) * gstep[i];                   \
            asm volatile("cp.async.cg.shared.global [%0], [%1], 16;"              \
                         :: "r"(sb + soff[i]), "l"(gp));                          \
        }                                                                         \
        asm volatile("cp.async.commit_group;");                                   \
    }

    FC_ISSUE(0); FC_ISSUE(1);

    float acc[6][4];
#pragma unroll
    for (int t = 0; t < 6; t++)
#pragma unroll
        for (int e = 0; e < 4; e++) acc[t][e] = 0.f;

    // A per-lane base: a0=x2t[(k0+8c+tig)*16+g]; a1:+8(m); a2:+64(k+4); a3:+72
    const unsigned* apl = reinterpret_cast<const unsigned*>(g_x2t + k0 * 16 + tig * 16 + g);
    // B per-lane offsets within a stage (floats)
    int lofs0 = tig * FC_WLD + g;
    int lofs1 = (tig + 4) * FC_WLD + g;

    const float* wsw = ws + wid * FC_WARP_FLOATS;
    for (int c = 0; c < NCHUNK; c++) {
        asm volatile("cp.async.wait_group 1;");
        __syncwarp();

        unsigned a0 = __ldg(apl + c * 128);
        unsigned a1 = __ldg(apl + c * 128 + 8);
        unsigned a2 = __ldg(apl + c * 128 + 64);
        unsigned a3 = __ldg(apl + c * 128 + 72);

        const float* buf = wsw + (c % FC_STAGES) * FC_STAGE_FLOATS;
#pragma unroll
        for (int t = 0; t < 6; t++) {
            unsigned b0 = __float_as_uint(buf[lofs0 + t * 8]);
            unsigned b1 = __float_as_uint(buf[lofs1 + t * 8]);
            mma_tf32(acc[t], a0, a1, a2, a3, b0, b1);
        }

        if (c + 2 < NCHUNK) FC_ISSUE(c + 2);
    }
    asm volatile("cp.async.wait_group 0;");
    __syncwarp();

    // epilogue: direct atomics. c0:(m=g, n=tig*2) c1:+1n c2:(m=g+8) c3:+1n
#pragma unroll
    for (int t = 0; t < 6; t++) {
        int col = wid * 48 + t * 8 + tig * 2;
        float* base = (col < 512) ? (g_ypre + col * 16) : (g_zpre + (col - 512) * 16);
        atomicAdd(base + g, acc[t][0]);
        atomicAdd(base + 16 + g, acc[t][1]);
        atomicAdd(base + g + 8, acc[t][2]);
        atomicAdd(base + 16 + g + 8, acc[t][3]);
    }
#undef FC_ISSUE
}

// ---------------- tail1: {split-K y2 (8 CTAs)} || {fused z-chain (1 CTA)} ----
__global__ void __launch_bounds__(128) tail1_kernel(const float* __restrict__ w256a,
                                                    const float* __restrict__ w128a,
                                                    const float* __restrict__ b128a,
                                                    const float* __restrict__ w128b,
                                                    const float* __restrict__ b128b,
                                                    const float* __restrict__ w64,
                                                    const float* __restrict__ b64) {
    __shared__ float xs[384 * 16];
    int tid = threadIdx.x;

    if (blockIdx.x < 8) {
        int nb = blockIdx.x & 1, kh = blockIdx.x >> 1;
        const float* ip = g_ypre + kh * 128 * 16;
        for (int idx = tid; idx < 128 * 16; idx += 128) xs[idx] = leaky_f(ip[idx]);
        __syncthreads();

        int n2 = nb * 128 + tid;
        float acc[16];
#pragma unroll
        for (int b = 0; b < 16; b++) acc[b] = 0.f;
        const float* wp = w256a + (size_t)kh * 128 * 256 + n2;
#pragma unroll 8
        for (int k = 0; k < 128; k++) {
            float wv = __ldg(wp + (size_t)k * 256);
#pragma unroll
            for (int b = 0; b < 16; b++) acc[b] = fmaf(wv, xs[k * 16 + b], acc[b]);
        }
#pragma unroll
        for (int b = 0; b < 16; b++) atomicAdd(g_y2 + n2 * 16 + b, acc[b]);
    } else {
        float* xa = xs;
        float* xb = xs + 256 * 16;
        for (int idx = tid; idx < 256 * 16; idx += 128) xa[idx] = leaky_f(g_zpre[idx]);
        __syncthreads();

        {
            float acc[16];
#pragma unroll
            for (int b = 0; b < 16; b++) acc[b] = 0.f;
#pragma unroll 8
            for (int k = 0; k < 256; k++) {
                float wv = __ldg(w128a + (size_t)k * 128 + tid);
#pragma unroll
                for (int b = 0; b < 16; b++) acc[b] = fmaf(wv, xa[k * 16 + b], acc[b]);
            }
            float bb = b128a[tid];
#pragma unroll
            for (int b = 0; b < 16; b++) xb[tid * 16 + b] = leaky_f(acc[b] + bb);
        }
        __syncthreads();

        {
            float acc[16];
#pragma unroll
            for (int b = 0; b < 16; b++) acc[b] = 0.f;
#pragma unroll 8
            for (int k = 0; k < 128; k++) {
                float wv = __ldg(w128b + (size_t)k * 128 + tid);
#pragma unroll
                for (int b = 0; b < 16; b++) acc[b] = fmaf(wv, xb[k * 16 + b], acc[b]);
            }
            float bb = b128b[tid];
#pragma unroll
            for (int b = 0; b < 16; b++) xa[tid * 16 + b] = leaky_f(acc[b] + bb);
        }
        __syncthreads();

        if (tid < 64) {
            float acc[16];
#pragma unroll
            for (int b = 0; b < 16; b++) acc[b] = 0.f;
#pragma unroll 8
            for (int k = 0; k < 128; k++) {
                float wv = __ldg(w64 + (size_t)k * 64 + tid);
#pragma unroll
                for (int b = 0; b < 16; b++) acc[b] = fmaf(wv, xa[k * 16 + b], acc[b]);
            }
            float bb = b64[tid];
#pragma unroll
            for (int b = 0; b < 16; b++) g_z4[tid * 16 + b] = acc[b] + bb;
        }
    }
}

// ---------------- tail2: {split-K y3 (46 CTAs)} || {z5 FC (8 CTAs)} ---------
__global__ void __launch_bounds__(128) tail2_kernel(const float* __restrict__ wcls,
                                                    const float* __restrict__ wreg,
                                                    const float* __restrict__ breg) {
    __shared__ float xs[128 * 16];
    int tid = threadIdx.x;

    if (blockIdx.x < 46) {
        int nb = blockIdx.x % 23, kh = blockIdx.x / 23;
        const float* ip = g_y2 + kh * 128 * 16;
        for (int idx = tid; idx < 128 * 16; idx += 128) xs[idx] = leaky_f(ip[idx]);
        __syncthreads();

        int n2 = nb * 128 + tid;
        if (n2 < 2925) {
            float acc[16];
#pragma unroll
            for (int b = 0; b < 16; b++) acc[b] = 0.f;
            const float* wp = wcls + (size_t)kh * 128 * 2925 + n2;
#pragma unroll 8
            for (int k = 0; k < 128; k++) {
                float wv = __ldg(wp + (size_t)k * 2925);
#pragma unroll
                for (int b = 0; b < 16; b++) acc[b] = fmaf(wv, xs[k * 16 + b], acc[b]);
            }
#pragma unroll
            for (int b = 0; b < 16; b++) atomicAdd(g_y3 + n2 * 16 + b, acc[b]);
        }
    } else {
        int bx = blockIdx.x - 46;
        for (int idx = tid; idx < 64 * 16; idx += 128) xs[idx] = leaky_f(g_z4[idx]);
        __syncthreads();

        int n2 = bx * 128 + tid;
        if (n2 < 900) {
            float acc[16];
#pragma unroll
            for (int b = 0; b < 16; b++) acc[b] = 0.f;
#pragma unroll 8
            for (int k = 0; k < 64; k++) {
                float wv = __ldg(wreg + (size_t)k * 900 + n2);
#pragma unroll
                for (int b = 0; b < 16; b++) acc[b] = fmaf(wv, xs[k * 16 + b], acc[b]);
            }
            float bb = breg[n2];
#pragma unroll
            for (int b = 0; b < 16; b++) g_z5[n2 * 16 + b] = acc[b] + bb;
        }
    }
}

// ---------------- heads: softmax(leaky(y3)@wsm+bsm), sigmoid(leaky(z5)@wsig+bsig)
__global__ void heads_kernel(const float* __restrict__ wsm, const float* __restrict__ bsm,
                             const float* __restrict__ wsig, const float* __restrict__ bsig,
                             float* __restrict__ out) {
    int idx = blockIdx.x * 256 + threadIdx.x;
    if (idx < 3600) {
        int b = idx / 225, p = idx % 225;
        float yv[13];
#pragma unroll
        for (int i = 0; i < 13; i++) yv[i] = leaky_f(g_y3[(p * 13 + i) * 16 + b]);
        float l[13];
        float m = -1e30f;
#pragma unroll
        for (int o = 0; o < 13; o++) {
            float s = bsm[o];
#pragma unroll
            for (int i = 0; i < 13; i++) s = fmaf(yv[i], wsm[i * 13 + o], s);
            l[o] = s;
            m = fmaxf(m, s);
        }
        float sum = 0.f;
#pragma unroll
        for (int o = 0; o < 13; o++) { l[o] = expf(l[o] - m); sum += l[o]; }
        float inv = 1.f / sum;
        float* dst = out + (size_t)(b * 225 + p) * 13;
#pragma unroll
        for (int o = 0; o < 13; o++) dst[o] = l[o] * inv;
    } else if (idx < 7200) {
        int j = idx - 3600;
        int b = j / 225, p = j % 225;
        float zv[4];
#pragma unroll
        for (int i = 0; i < 4; i++) zv[i] = leaky_f(g_z5[(p * 4 + i) * 16 + b]);
        float* dst = out + 46800 + (size_t)(b * 225 + p) * 4;
#pragma unroll
        for (int o = 0; o < 4; o++) {
            float s = bsig[o];
#pragma unroll
            for (int i = 0; i < 4; i++) s = fmaf(zv[i], wsig[i * 4 + o], s);
            dst[o] = 1.f / (1.f + expf(-s));
        }
    }
}

// ---------------- launch ----------------------------------------------------
extern "C" void kernel_launch(void* const* d_in, const int* in_sizes, int n_in,
                              void* d_out, int out_size) {
    const float* hidden  = (const float*)d_in[0];
    const float* conv1_w = (const float*)d_in[1];
    const float* conv1_b = (const float*)d_in[2];
    const float* conv2_w = (const float*)d_in[3];
    const float* conv2_b = (const float*)d_in[4];
    const float* w512    = (const float*)d_in[5];
    const float* b512    = (const float*)d_in[6];
    const float* w256a   = (const float*)d_in[7];
    const float* b256a   = (const float*)d_in[8];
    const float* wcls    = (const float*)d_in[9];
    const float* bcls    = (const float*)d_in[10];
    const float* wsm     = (const float*)d_in[11];
    const float* bsm     = (const float*)d_in[12];
    const float* w256b   = (const float*)d_in[13];
    const float* b256b   = (const float*)d_in[14];
    const float* w128a   = (const float*)d_in[15];
    const float* b128a   = (const float*)d_in[16];
    const float* w128b   = (const float*)d_in[17];
    const float* b128b   = (const float*)d_in[18];
    const float* w64     = (const float*)d_in[19];
    const float* b64     = (const float*)d_in[20];
    const float* wreg    = (const float*)d_in[21];
    const float* breg    = (const float*)d_in[22];
    const float* wsig    = (const float*)d_in[23];
    const float* bsig    = (const float*)d_in[24];
    float* out = (float*)d_out;

    static bool attr_set = false;
    if (!attr_set) {
        cudaFuncSetAttribute(conv2_kernel, cudaFuncAttributeMaxDynamicSharedMemorySize, CV2_SMEM_BYTES);
        cudaFuncSetAttribute(fcbig_tf32_kernel, cudaFuncAttributeMaxDynamicSharedMemorySize, FC_SMEM_BYTES);
        attr_set = true;
    }

    prep_kernel<<<183, 256>>>(conv2_w, b512, b256b, bcls, b256a);
    conv1_kernel<<<dim3(P1H, BATCH), 256>>>(hidden, conv1_w, conv1_b);
    conv2_kernel<<<dim3(6, 24, BATCH), 256, CV2_SMEM_BYTES>>>(conv2_b);
    xpose_kernel<<<NSLICES, 256>>>();
    fcbig_tf32_kernel<<<NSLICES, 512, FC_SMEM_BYTES>>>(w512, w256b);

    tail1_kernel<<<9, 128>>>(w256a, w128a, b128a, w128b, b128b, w64, b64);
    tail2_kernel<<<54, 128>>>(wcls, wreg, breg);

    heads_kernel<<<29, 256>>>(wsm, bsm, wsig, bsig, out);
}

// round 15
// speedup vs baseline: 1.4597x; 1.0150x over previous
#include <cuda_runtime.h>
#include <cuda_bf16.h>
#include <mma.h>
#include <math.h>

using namespace nvcuda;

#define BATCH 16
#define P1H 97
#define P1W 383
#define C1 32
#define P2H 47
#define P2W 190
#define C2 64
#define FLAT 571520          // 47*190*64
#define KSLICE 640           // 893 * 640 = 571520 exactly
#define NSLICES 893
#define NCHUNK 80            // KSLICE / 8
#define FC_STAGES 3
#define FC_WLD 52                               // 48 cols + 4 pad floats per k-row
#define FC_STAGE_FLOATS (8 * FC_WLD)            // 416 floats per stage
#define FC_WARP_FLOATS (FC_STAGES * FC_STAGE_FLOATS)   // 1248
#define FC_SMEM_BYTES (16 * FC_WARP_FLOATS * 4)        // 79,872 B -> 2 CTAs/SM

// conv2 wide-tile geometry: 64 conv cols per CTA
#define CV2_APITCH 2112                          // 66 cols * 32 ch (halfs) per row
#define CV2_BPAD 72
#define CV2_SMEM_BYTES ((6 * CV2_APITCH + 288 * CV2_BPAD) * 2)   // 66,816 B

// ---------------- scratch (device globals; allocations are forbidden) -------
__device__ __align__(128) __nv_bfloat16 g_x1b[(size_t)BATCH * P1H * P1W * C1]; // conv1 out bf16
__device__ __align__(16)  __nv_bfloat16 g_w2b[288 * 64];                       // conv2 weights bf16
__device__ __align__(16)  float g_x2[(size_t)BATCH * FLAT];                    // conv2 out [b][k]
__device__ __align__(128) float g_x2t[(size_t)FLAT * 16];                      // transposed [k][b]
__device__ float g_ypre[512 * 16];   // [n][b]
__device__ float g_zpre[256 * 16];
__device__ float g_y2[256 * 16];
__device__ float g_y3[2925 * 16];
__device__ float g_z4[64 * 16];
__device__ float g_z5[900 * 16];

__device__ __forceinline__ float leaky_f(float x) { return x >= 0.f ? x : 0.01f * x; }

__device__ __forceinline__ unsigned long long pack2(float a, float b) {
    unsigned long long r;
    asm("mov.b64 %0, {%1, %2};" : "=l"(r) : "f"(a), "f"(b));
    return r;
}
__device__ __forceinline__ float2 unpack2(unsigned long long v) {
    float2 r;
    asm("mov.b64 {%0, %1}, %2;" : "=f"(r.x), "=f"(r.y) : "l"(v));
    return r;
}
__device__ __forceinline__ void ffma2(unsigned long long& acc, unsigned long long a, unsigned long long b) {
    asm("fma.rn.f32x2 %0, %1, %2, %0;" : "+l"(acc) : "l"(a), "l"(b));
}

// raw tf32 mma m16n8k8 (documented fragment layout; acc in place)
__device__ __forceinline__ void mma_tf32(float (&d)[4],
                                         unsigned a0, unsigned a1, unsigned a2, unsigned a3,
                                         unsigned b0, unsigned b1) {
    asm volatile(
        "mma.sync.aligned.m16n8k8.row.col.f32.tf32.tf32.f32 "
        "{%0,%1,%2,%3},{%4,%5,%6,%7},{%8,%9},{%0,%1,%2,%3};"
        : "+f"(d[0]), "+f"(d[1]), "+f"(d[2]), "+f"(d[3])
        : "r"(a0), "r"(a1), "r"(a2), "r"(a3), "r"(b0), "r"(b1));
}

// ---------------- prep: conv2 weight -> bf16 ; bias-init split-K accumulators
__global__ void prep_kernel(const float* __restrict__ w2,
                            const float* __restrict__ b512,
                            const float* __restrict__ b256b,
                            const float* __restrict__ bcls,
                            const float* __restrict__ b256a) {
    int i = blockIdx.x * 256 + threadIdx.x;
    if (i < 288 * 64) g_w2b[i] = __float2bfloat16(w2[i]);
    if (i < 512 * 16) g_ypre[i] = b512[i >> 4];
    if (i < 256 * 16) g_zpre[i] = b256b[i >> 4];
    if (i < 256 * 16) g_y2[i] = b256a[i >> 4];
    if (i < 2925 * 16) g_y3[i] = bcls[i >> 4];
}

// ---------------- conv1 (3x3, 1->32) + relu + maxpool2, fused, bf16 output --
__global__ void __launch_bounds__(256) conv1_kernel(const float* __restrict__ hidden,
                                                    const float* __restrict__ w1,
                                                    const float* __restrict__ b1) {
    __shared__ float ins[4 * 768];
    __shared__ float w1s[9 * 32];
    __shared__ float b1s[32];
    int b = blockIdx.y, ph = blockIdx.x;
    int tid = threadIdx.x;

    const float* src = hidden + ((size_t)b * 197 + 2 * ph) * 768;
    for (int i = tid; i < 4 * 768; i += 256) ins[i] = src[i];
    if (tid < 288) w1s[tid] = w1[tid];
    if (tid < 32) b1s[tid] = b1[tid];
    __syncthreads();

    int cg = tid >> 6;
    int pwl = tid & 63;
    int c0 = cg * 8;

    unsigned long long wv2[9][4];
#pragma unroll
    for (int t = 0; t < 9; t++)
#pragma unroll
        for (int p = 0; p < 4; p++)
            wv2[t][p] = pack2(w1s[t * 32 + c0 + 2 * p], w1s[t * 32 + c0 + 2 * p + 1]);

    for (int it = 0; it < 6; it++) {
        int pw = it * 64 + pwl;
        if (pw >= 383) break;
        float in[4][4];
#pragma unroll
        for (int r = 0; r < 4; r++)
#pragma unroll
            for (int c = 0; c < 4; c++) in[r][c] = ins[r * 768 + 2 * pw + c];

        unsigned long long acc2[2][2][4];
#pragma unroll
        for (int i = 0; i < 2; i++)
#pragma unroll
            for (int j = 0; j < 2; j++)
#pragma unroll
                for (int p = 0; p < 4; p++) acc2[i][j][p] = 0ull;

#pragma unroll
        for (int t = 0; t < 9; t++) {
            int kh = t / 3, kw = t % 3;
#pragma unroll
            for (int i = 0; i < 2; i++)
#pragma unroll
                for (int j = 0; j < 2; j++) {
                    float x = in[i + kh][j + kw];
                    unsigned long long xx = pack2(x, x);
#pragma unroll
                    for (int p = 0; p < 4; p++)
                        ffma2(acc2[i][j][p], wv2[t][p], xx);
                }
        }

        size_t o = (((size_t)b * P1H + ph) * P1W + pw) * C1 + c0;
        __nv_bfloat162* dst = reinterpret_cast<__nv_bfloat162*>(g_x1b + o);
#pragma unroll
        for (int p = 0; p < 4; p++) {
            float2 a00 = unpack2(acc2[0][0][p]);
            float2 a01 = unpack2(acc2[0][1][p]);
            float2 a10 = unpack2(acc2[1][0][p]);
            float2 a11 = unpack2(acc2[1][1][p]);
            float m0 = fmaxf(fmaxf(a00.x, a01.x), fmaxf(a10.x, a11.x));
            float m1 = fmaxf(fmaxf(a00.y, a01.y), fmaxf(a10.y, a11.y));
            dst[p] = __floats2bfloat162_rn(fmaxf(m0 + b1s[c0 + 2 * p], 0.f),
                                           fmaxf(m1 + b1s[c0 + 2 * p + 1], 0.f));
        }
    }
}

// ---------------- conv2 (3x3, 32->64) bf16 wmma implicit GEMM + relu + pool --
__global__ void __launch_bounds__(256, 2) conv2_kernel(const float* __restrict__ b2) {
    extern __shared__ __align__(16) __nv_bfloat16 smem_h[];
    __nv_bfloat16* x1s = smem_h;
    __nv_bfloat16* w2s = smem_h + 6 * CV2_APITCH;

    int wt = blockIdx.x;        // 0..5
    int pb = blockIdx.y;        // 0..23
    int b = blockIdx.z;         // 0..15
    int tid = threadIdx.x;
    int h0 = 4 * pb;
    int w0 = wt * 64;

    for (int i = tid; i < 6 * 264; i += 256) {
        int r = i / 264, q = i - r * 264;
        int row = h0 + r; if (row > 96) row = 96;
        int col = w0 + (q >> 2); if (col > 382) col = 382;
        const uint4 v = *(const uint4*)(g_x1b + (((size_t)b * P1H + row) * P1W + col) * C1 + (q & 3) * 8);
        *(uint4*)(x1s + (size_t)r * CV2_APITCH + q * 8) = v;
    }
    for (int i = tid; i < 2304; i += 256) {
        int k = i >> 3, n0 = (i & 7) * 8;
        uint4 v = *(const uint4*)(g_w2b + k * 64 + n0);
        *(uint4*)(w2s + k * CV2_BPAD + n0) = v;
    }
    __syncthreads();

    int wid = tid >> 5;
    int rloc = wid >> 1;
    int hOff = (wid & 1) * 32;

    wmma::fragment<wmma::matrix_a, 16, 16, 16, __nv_bfloat16, wmma::row_major> af[2];
    wmma::fragment<wmma::matrix_b, 16, 16, 16, __nv_bfloat16, wmma::row_major> bf;
    wmma::fragment<wmma::accumulator, 16, 16, 16, float> acc[2][4];
#pragma unroll
    for (int mt = 0; mt < 2; mt++)
#pragma unroll
        for (int nf = 0; nf < 4; nf++) wmma::fill_fragment(acc[mt][nf], 0.f);

#pragma unroll
    for (int kh = 0; kh < 3; kh++) {
        const __nv_bfloat16* base = x1s + (rloc + kh) * CV2_APITCH + hOff * 32;
#pragma unroll
        for (int jc = 0; jc < 6; jc++) {
            wmma::load_matrix_sync(af[0], base + jc * 16, 32);
            wmma::load_matrix_sync(af[1], base + 512 + jc * 16, 32);
            const __nv_bfloat16* bp = w2s + (kh * 96 + jc * 16) * CV2_BPAD;
#pragma unroll
            for (int nf = 0; nf < 4; nf++) {
                wmma::load_matrix_sync(bf, bp + nf * 16, CV2_BPAD);
                wmma::mma_sync(acc[0][nf], af[0], bf, acc[0][nf]);
                wmma::mma_sync(acc[1][nf], af[1], bf, acc[1][nf]);
            }
        }
    }

    __syncthreads();
    float* cs = reinterpret_cast<float*>(smem_h);
#pragma unroll
    for (int mt = 0; mt < 2; mt++)
#pragma unroll
        for (int nf = 0; nf < 4; nf++)
            wmma::store_matrix_sync(cs + (wid * 2 + mt) * 1024 + nf * 16, acc[mt][nf],
                                    64, wmma::mem_row_major);
    __syncthreads();

#pragma unroll
    for (int it = 0; it < 2; it++) {
        int idx = it * 256 + tid;
        int pr = idx >> 8;
        int pj = (idx >> 3) & 31;
        int c0 = (idx & 7) * 8;
        int ph2 = 2 * pb + pr;
        int pwg = wt * 32 + pj;
        if (ph2 < P2H && pwg < P2W) {
            float v[8];
#pragma unroll
            for (int cc = 0; cc < 8; cc++) {
                int c = c0 + cc;
                float m = -1e30f;
#pragma unroll
                for (int i = 0; i < 2; i++)
#pragma unroll
                    for (int j = 0; j < 2; j++) {
                        int rr = 2 * pr + i;
                        int jj = 2 * pj + j;
                        m = fmaxf(m, cs[((rr * 2 + (jj >> 5)) * 2 + ((jj >> 4) & 1)) * 1024
                                        + (jj & 15) * 64 + c]);
                    }
                v[cc] = fmaxf(m + b2[c], 0.f);
            }
            size_t o = (size_t)b * FLAT + ((size_t)ph2 * P2W + pwg) * C2 + c0;
            float4 o0 = {v[0], v[1], v[2], v[3]};
            float4 o1 = {v[4], v[5], v[6], v[7]};
            *reinterpret_cast<float4*>(g_x2 + o) = o0;
            *reinterpret_cast<float4*>(g_x2 + o + 4) = o1;
        }
    }
}

// ---------------- transpose x2[b][k] -> x2t[k][b] ----------------------------
// b-outer load loop (no division), streaming loads, float4 stores.
__global__ void __launch_bounds__(256) xpose_kernel() {
    __shared__ float s[640 * 17];
    size_t k0 = (size_t)blockIdx.x * 640;
    int tid = threadIdx.x;
#pragma unroll
    for (int b = 0; b < 16; b++) {
        const float* src = g_x2 + (size_t)b * FLAT + k0;
#pragma unroll
        for (int u = 0; u < 3; u++) {           // 640 = 256*2 + 128
            int kk = tid + u * 256;
            if (kk < 640) s[kk * 17 + b] = __ldcs(src + kk);
        }
    }
    __syncthreads();
    // 2560 float4 stores: idx -> k = idx>>2, quad q = (idx&3)*4
    for (int idx = tid; idx < 2560; idx += 256) {
        int k = idx >> 2, q = (idx & 3) * 4;
        const float* sp = s + k * 17 + q;
        float4 v = {sp[0], sp[1], sp[2], sp[3]};
        *reinterpret_cast<float4*>(g_x2t + (k0 + k) * 16 + q) = v;
    }
}

// ---------------- big FC via raw tf32 mma.sync, warp-private cp.async rings --
// [FROZEN — best measured config]
__global__ void __launch_bounds__(512, 2) fcbig_tf32_kernel(const float* __restrict__ w512,
                                                            const float* __restrict__ w256b) {
    extern __shared__ __align__(16) float ws[];  // [16 warps][3 stages][8][FC_WLD]

    int tid = threadIdx.x;
    int wid = tid >> 5;
    int lane = tid & 31;
    int g = lane >> 2;        // groupID 0..7
    int tig = lane & 3;       // thread-in-group 0..3
    size_t k0 = (size_t)blockIdx.x * KSLICE;

    const float* gsrc[3];
    int gstep[3];
    unsigned soff[3];
#pragma unroll
    for (int i = 0; i < 3; i++) {
        int idx = lane + i * 32;
        int r = idx / 12;
        int c4 = idx - r * 12;
        int gcol = wid * 48 + c4 * 4;
        if (gcol < 512) { gsrc[i] = w512  + (k0 + r) * 512 + gcol;         gstep[i] = 8 * 512; }
        else            { gsrc[i] = w256b + (k0 + r) * 256 + (gcol - 512); gstep[i] = 8 * 256; }
        soff[i] = (unsigned)((r * FC_WLD + c4 * 4) * 4);
    }
    unsigned wbase = (unsigned)__cvta_generic_to_shared(ws) + wid * (FC_WARP_FLOATS * 4);

#define FC_ISSUE(c)                                                               \
    {                                                                             \
        unsigned sb = wbase + ((c) % FC_STAGES) * (FC_STAGE_FLOATS * 4);          \
        _Pragma("unroll")                                                         \
        for (int i = 0; i < 3; i++) {                                             \
            const float* gp = gsrc[i] + (size_t)(c) * gstep[i];                   \
            asm volatile("cp.async.cg.shared.global [%0], [%1], 16;"              \
                         :: "r"(sb + soff[i]), "l"(gp));                          \
        }                                                                         \
        asm volatile("cp.async.commit_group;");                                   \
    }

    FC_ISSUE(0); FC_ISSUE(1);

    float acc[6][4];
#pragma unroll
    for (int t = 0; t < 6; t++)
#pragma unroll
        for (int e = 0; e < 4; e++) acc[t][e] = 0.f;

    const unsigned* apl = reinterpret_cast<const unsigned*>(g_x2t + k0 * 16 + tig * 16 + g);
    int lofs0 = tig * FC_WLD + g;
    int lofs1 = (tig + 4) * FC_WLD + g;

    const float* wsw = ws + wid * FC_WARP_FLOATS;
    for (int c = 0; c < NCHUNK; c++) {
        asm volatile("cp.async.wait_group 1;");
        __syncwarp();

        unsigned a0 = __ldg(apl + c * 128);
        unsigned a1 = __ldg(apl + c * 128 + 8);
        unsigned a2 = __ldg(apl + c * 128 + 64);
        unsigned a3 = __ldg(apl + c * 128 + 72);

        const float* buf = wsw + (c % FC_STAGES) * FC_STAGE_FLOATS;
#pragma unroll
        for (int t = 0; t < 6; t++) {
            unsigned b0 = __float_as_uint(buf[lofs0 + t * 8]);
            unsigned b1 = __float_as_uint(buf[lofs1 + t * 8]);
            mma_tf32(acc[t], a0, a1, a2, a3, b0, b1);
        }

        if (c + 2 < NCHUNK) FC_ISSUE(c + 2);
    }
    asm volatile("cp.async.wait_group 0;");
    __syncwarp();

#pragma unroll
    for (int t = 0; t < 6; t++) {
        int col = wid * 48 + t * 8 + tig * 2;
        float* base = (col < 512) ? (g_ypre + col * 16) : (g_zpre + (col - 512) * 16);
        atomicAdd(base + g, acc[t][0]);
        atomicAdd(base + 16 + g, acc[t][1]);
        atomicAdd(base + g + 8, acc[t][2]);
        atomicAdd(base + 16 + g + 8, acc[t][3]);
    }
#undef FC_ISSUE
}

// ---------------- tail1: {split-K y2 (8 CTAs)} || {fused z-chain (1 CTA)} ----
__global__ void __launch_bounds__(128) tail1_kernel(const float* __restrict__ w256a,
                                                    const float* __restrict__ w128a,
                                                    const float* __restrict__ b128a,
                                                    const float* __restrict__ w128b,
                                                    const float* __restrict__ b128b,
                                                    const float* __restrict__ w64,
                                                    const float* __restrict__ b64) {
    __shared__ float xs[384 * 16];
    int tid = threadIdx.x;

    if (blockIdx.x < 8) {
        int nb = blockIdx.x & 1, kh = blockIdx.x >> 1;
        const float* ip = g_ypre + kh * 128 * 16;
        for (int idx = tid; idx < 128 * 16; idx += 128) xs[idx] = leaky_f(ip[idx]);
        __syncthreads();

        int n2 = nb * 128 + tid;
        float acc[16];
#pragma unroll
        for (int b = 0; b < 16; b++) acc[b] = 0.f;
        const float* wp = w256a + (size_t)kh * 128 * 256 + n2;
#pragma unroll 8
        for (int k = 0; k < 128; k++) {
            float wv = __ldg(wp + (size_t)k * 256);
#pragma unroll
            for (int b = 0; b < 16; b++) acc[b] = fmaf(wv, xs[k * 16 + b], acc[b]);
        }
#pragma unroll
        for (int b = 0; b < 16; b++) atomicAdd(g_y2 + n2 * 16 + b, acc[b]);
    } else {
        float* xa = xs;
        float* xb = xs + 256 * 16;
        for (int idx = tid; idx < 256 * 16; idx += 128) xa[idx] = leaky_f(g_zpre[idx]);
        __syncthreads();

        {
            float acc[16];
#pragma unroll
            for (int b = 0; b < 16; b++) acc[b] = 0.f;
#pragma unroll 8
            for (int k = 0; k < 256; k++) {
                float wv = __ldg(w128a + (size_t)k * 128 + tid);
#pragma unroll
                for (int b = 0; b < 16; b++) acc[b] = fmaf(wv, xa[k * 16 + b], acc[b]);
            }
            float bb = b128a[tid];
#pragma unroll
            for (int b = 0; b < 16; b++) xb[tid * 16 + b] = leaky_f(acc[b] + bb);
        }
        __syncthreads();

        {
            float acc[16];
#pragma unroll
            for (int b = 0; b < 16; b++) acc[b] = 0.f;
#pragma unroll 8
            for (int k = 0; k < 128; k++) {
                float wv = __ldg(w128b + (size_t)k * 128 + tid);
#pragma unroll
                for (int b = 0; b < 16; b++) acc[b] = fmaf(wv, xb[k * 16 + b], acc[b]);
            }
            float bb = b128b[tid];
#pragma unroll
            for (int b = 0; b < 16; b++) xa[tid * 16 + b] = leaky_f(acc[b] + bb);
        }
        __syncthreads();

        if (tid < 64) {
            float acc[16];
#pragma unroll
            for (int b = 0; b < 16; b++) acc[b] = 0.f;
#pragma unroll 8
            for (int k = 0; k < 128; k++) {
                float wv = __ldg(w64 + (size_t)k * 64 + tid);
#pragma unroll
                for (int b = 0; b < 16; b++) acc[b] = fmaf(wv, xa[k * 16 + b], acc[b]);
            }
            float bb = b64[tid];
#pragma unroll
            for (int b = 0; b < 16; b++) g_z4[tid * 16 + b] = acc[b] + bb;
        }
    }
}

// ---------------- tail2: {split-K y3 (46 CTAs)} || {z5 FC (8 CTAs)} ---------
__global__ void __launch_bounds__(128) tail2_kernel(const float* __restrict__ wcls,
                                                    const float* __restrict__ wreg,
                                                    const float* __restrict__ breg) {
    __shared__ float xs[128 * 16];
    int tid = threadIdx.x;

    if (blockIdx.x < 46) {
        int nb = blockIdx.x % 23, kh = blockIdx.x / 23;
        const float* ip = g_y2 + kh * 128 * 16;
        for (int idx = tid; idx < 128 * 16; idx += 128) xs[idx] = leaky_f(ip[idx]);
        __syncthreads();

        int n2 = nb * 128 + tid;
        if (n2 < 2925) {
            float acc[16];
#pragma unroll
            for (int b = 0; b < 16; b++) acc[b] = 0.f;
            const float* wp = wcls + (size_t)kh * 128 * 2925 + n2;
#pragma unroll 8
            for (int k = 0; k < 128; k++) {
                float wv = __ldg(wp + (size_t)k * 2925);
#pragma unroll
                for (int b = 0; b < 16; b++) acc[b] = fmaf(wv, xs[k * 16 + b], acc[b]);
            }
#pragma unroll
            for (int b = 0; b < 16; b++) atomicAdd(g_y3 + n2 * 16 + b, acc[b]);
        }
    } else {
        int bx = blockIdx.x - 46;
        for (int idx = tid; idx < 64 * 16; idx += 128) xs[idx] = leaky_f(g_z4[idx]);
        __syncthreads();

        int n2 = bx * 128 + tid;
        if (n2 < 900) {
            float acc[16];
#pragma unroll
            for (int b = 0; b < 16; b++) acc[b] = 0.f;
#pragma unroll 8
            for (int k = 0; k < 64; k++) {
                float wv = __ldg(wreg + (size_t)k * 900 + n2);
#pragma unroll
                for (int b = 0; b < 16; b++) acc[b] = fmaf(wv, xs[k * 16 + b], acc[b]);
            }
            float bb = breg[n2];
#pragma unroll
            for (int b = 0; b < 16; b++) g_z5[n2 * 16 + b] = acc[b] + bb;
        }
    }
}

// ---------------- heads: softmax(leaky(y3)@wsm+bsm), sigmoid(leaky(z5)@wsig+bsig)
__global__ void heads_kernel(const float* __restrict__ wsm, const float* __restrict__ bsm,
                             const float* __restrict__ wsig, const float* __restrict__ bsig,
                             float* __restrict__ out) {
    int idx = blockIdx.x * 256 + threadIdx.x;
    if (idx < 3600) {
        int b = idx / 225, p = idx % 225;
        float yv[13];
#pragma unroll
        for (int i = 0; i < 13; i++) yv[i] = leaky_f(g_y3[(p * 13 + i) * 16 + b]);
        float l[13];
        float m = -1e30f;
#pragma unroll
        for (int o = 0; o < 13; o++) {
            float s = bsm[o];
#pragma unroll
            for (int i = 0; i < 13; i++) s = fmaf(yv[i], wsm[i * 13 + o], s);
            l[o] = s;
            m = fmaxf(m, s);
        }
        float sum = 0.f;
#pragma unroll
        for (int o = 0; o < 13; o++) { l[o] = expf(l[o] - m); sum += l[o]; }
        float inv = 1.f / sum;
        float* dst = out + (size_t)(b * 225 + p) * 13;
#pragma unroll
        for (int o = 0; o < 13; o++) dst[o] = l[o] * inv;
    } else if (idx < 7200) {
        int j = idx - 3600;
        int b = j / 225, p = j % 225;
        float zv[4];
#pragma unroll
        for (int i = 0; i < 4; i++) zv[i] = leaky_f(g_z5[(p * 4 + i) * 16 + b]);
        float* dst = out + 46800 + (size_t)(b * 225 + p) * 4;
#pragma unroll
        for (int o = 0; o < 4; o++) {
            float s = bsig[o];
#pragma unroll
            for (int i = 0; i < 4; i++) s = fmaf(zv[i], wsig[i * 4 + o], s);
            dst[o] = 1.f / (1.f + expf(-s));
        }
    }
}

// ---------------- launch ----------------------------------------------------
extern "C" void kernel_launch(void* const* d_in, const int* in_sizes, int n_in,
                              void* d_out, int out_size) {
    const float* hidden  = (const float*)d_in[0];
    const float* conv1_w = (const float*)d_in[1];
    const float* conv1_b = (const float*)d_in[2];
    const float* conv2_w = (const float*)d_in[3];
    const float* conv2_b = (const float*)d_in[4];
    const float* w512    = (const float*)d_in[5];
    const float* b512    = (const float*)d_in[6];
    const float* w256a   = (const float*)d_in[7];
    const float* b256a   = (const float*)d_in[8];
    const float* wcls    = (const float*)d_in[9];
    const float* bcls    = (const float*)d_in[10];
    const float* wsm     = (const float*)d_in[11];
    const float* bsm     = (const float*)d_in[12];
    const float* w256b   = (const float*)d_in[13];
    const float* b256b   = (const float*)d_in[14];
    const float* w128a   = (const float*)d_in[15];
    const float* b128a   = (const float*)d_in[16];
    const float* w128b   = (const float*)d_in[17];
    const float* b128b   = (const float*)d_in[18];
    const float* w64     = (const float*)d_in[19];
    const float* b64     = (const float*)d_in[20];
    const float* wreg    = (const float*)d_in[21];
    const float* breg    = (const float*)d_in[22];
    const float* wsig    = (const float*)d_in[23];
    const float* bsig    = (const float*)d_in[24];
    float* out = (float*)d_out;

    static bool attr_set = false;
    if (!attr_set) {
        cudaFuncSetAttribute(conv2_kernel, cudaFuncAttributeMaxDynamicSharedMemorySize, CV2_SMEM_BYTES);
        cudaFuncSetAttribute(fcbig_tf32_kernel, cudaFuncAttributeMaxDynamicSharedMemorySize, FC_SMEM_BYTES);
        attr_set = true;
    }

    prep_kernel<<<183, 256>>>(conv2_w, b512, b256b, bcls, b256a);
    conv1_kernel<<<dim3(P1H, BATCH), 256>>>(hidden, conv1_w, conv1_b);
    conv2_kernel<<<dim3(6, 24, BATCH), 256, CV2_SMEM_BYTES>>>(conv2_b);
    xpose_kernel<<<NSLICES, 256>>>();
    fcbig_tf32_kernel<<<NSLICES, 512, FC_SMEM_BYTES>>>(w512, w256b);

    tail1_kernel<<<9, 128>>>(w256a, w128a, b128a, w128b, b128b, w64, b64);
    tail2_kernel<<<54, 128>>>(wcls, wreg, breg);

    heads_kernel<<<29, 256>>>(wsm, bsm, wsig, bsig, out);
}